// round 15
// baseline (speedup 1.0000x reference)
#include <cuda_runtime.h>
#include <math.h>
#include <stdint.h>

// ---------------- static scratch ----------------
__device__ float g_scratch[51904512];
__device__ float g_params[8][16];

static const size_t OFF_EP   = 0;
static const size_t OFF_LNX  = 12582912;
static const size_t OFF_Q    = 22020096;
static const size_t OFF_ATT  = 31457280;
static const size_t OFF_P0   = 34603008;
static const size_t OFF_Z0   = 37748736;
static const size_t OFF_HID  = 40894464;
static const size_t OFF_WQT  = 47185920;
static const size_t OFF_WPT  = 48955392;
static const size_t OFF_W1T  = 49545216;
static const size_t OFF_W2T  = 50724864;

// =========================================================================
// helpers
// =========================================================================
__device__ __forceinline__ uint32_t f2tf32(float f) {
    uint32_t u;
    asm("cvt.rna.tf32.f32 %0, %1;" : "=r"(u) : "f"(f));
    return u;
}
__device__ __forceinline__ float roundtf(float f) {
    return __uint_as_float(f2tf32(f));
}

__device__ __forceinline__ void mma_tf32(float d[4], const uint32_t a[4], const uint32_t b[2]) {
    asm volatile(
        "mma.sync.aligned.m16n8k8.row.col.f32.tf32.tf32.f32 "
        "{%0,%1,%2,%3}, {%4,%5,%6,%7}, {%8,%9}, {%0,%1,%2,%3};"
        : "+f"(d[0]), "+f"(d[1]), "+f"(d[2]), "+f"(d[3])
        : "r"(a[0]), "r"(a[1]), "r"(a[2]), "r"(a[3]), "r"(b[0]), "r"(b[1]));
}

__device__ __forceinline__ uint32_t smem_u32(const void* p) {
    uint32_t a;
    asm("{ .reg .u64 t; cvta.to.shared.u64 t, %1; cvt.u32.u64 %0, t; }" : "=r"(a) : "l"(p));
    return a;
}
__device__ __forceinline__ void cp_async16(uint32_t dst, const void* src) {
    asm volatile("cp.async.cg.shared.global [%0], [%1], 16;" :: "r"(dst), "l"(src));
}
#define CP_COMMIT() asm volatile("cp.async.commit_group;" ::: "memory")
#define CP_WAIT_ALL() asm volatile("cp.async.wait_group 0;" ::: "memory")

__device__ __forceinline__ void st_cs_f4(float* p, float4 v) {
    asm volatile("st.global.cs.v4.f32 [%0], {%1, %2, %3, %4};"
                 :: "l"(p), "f"(v.x), "f"(v.y), "f"(v.z), "f"(v.w) : "memory");
}

__device__ __forceinline__ float fast_sqrt(float x)  { float r; asm("sqrt.approx.f32 %0, %1;"  : "=f"(r) : "f"(x)); return r; }
__device__ __forceinline__ float fast_rsqrt(float x) { float r; asm("rsqrt.approx.f32 %0, %1;" : "=f"(r) : "f"(x)); return r; }
__device__ __forceinline__ float fast_rcp(float x)   { float r; asm("rcp.approx.f32 %0, %1;"   : "=f"(r) : "f"(x)); return r; }
__device__ __forceinline__ float fast_ex2(float x)   { float r; asm("ex2.approx.f32 %0, %1;"   : "=f"(r) : "f"(x)); return r; }

// =========================================================================
// merged weight transpose (unchanged)
// =========================================================================
__global__ void transpose_all_kernel(
    const float* __restrict__ Wq, const float* __restrict__ Wk,
    const float* __restrict__ Wv, const float* __restrict__ Wp,
    const float* __restrict__ W1, const float* __restrict__ W2,
    float* __restrict__ wqt, float* __restrict__ wkt,
    float* __restrict__ wvt, float* __restrict__ wpt,
    float* __restrict__ w1t, float* __restrict__ w2t) {
    __shared__ float t[32][33];
    int bid = blockIdx.x;
    const float* in;
    float* out;
    int R, C, tl;
    if (bid < 2304) {
        int seg = bid / 576;
        tl = bid - seg * 576;
        R = 768; C = 768;
        in  = (seg == 0) ? Wq  : (seg == 1) ? Wk  : (seg == 2) ? Wv  : Wp;
        out = (seg == 0) ? wqt : (seg == 1) ? wkt : (seg == 2) ? wvt : wpt;
    } else if (bid < 3456) {
        tl = bid - 2304;
        R = 768; C = 1536;
        in = W1; out = w1t;
    } else {
        tl = bid - 3456;
        R = 1536; C = 768;
        in = W2; out = w2t;
    }
    int tilesX = C >> 5;
    int c0 = (tl % tilesX) << 5, r0 = (tl / tilesX) << 5;
    int tx = threadIdx.x, ty = threadIdx.y;
    t[ty][tx] = in[(size_t)(r0 + ty) * C + c0 + tx];
    __syncthreads();
    out[(size_t)(c0 + ty) * R + r0 + tx] = roundtf(t[tx][ty]);
}

// =========================================================================
// cp.async double-buffered mma.sync tf32 GEMM body (unchanged)
// =========================================================================
__device__ __forceinline__ void gemm_body(
    const float* __restrict__ A, const float* __restrict__ Bt,
    const float* __restrict__ bias, float* __restrict__ C,
    int M, int N, int K, int act, uint32_t* dynsm) {
    int tid = threadIdx.x;
    int lane = tid & 31, warp = tid >> 5;
    int wm = warp >> 2, wn = warp & 3;
    int g = lane >> 2, t4 = lane & 3;
    int m0 = blockIdx.y << 7, n0 = blockIdx.x << 7;

    float acc[4][4][4];
#pragma unroll
    for (int i = 0; i < 4; i++)
#pragma unroll
        for (int j = 0; j < 4; j++)
#pragma unroll
            for (int r = 0; r < 4; r++) acc[i][j][r] = 0.f;

    int rowL[4], qL[4];
#pragma unroll
    for (int it = 0; it < 4; it++) {
        int e = (it << 8) + tid;
        rowL[it] = e >> 3;
        qL[it] = (e & 7) << 2;
    }
    const float* aPtr[4];
    const float* bPtr[4];
    uint32_t aOff[4], bOff[4];
    uint32_t sbase = smem_u32(dynsm);
#pragma unroll
    for (int it = 0; it < 4; it++) {
        aPtr[it] = A + (size_t)(m0 + rowL[it]) * K + qL[it];
        bPtr[it] = Bt + (size_t)(n0 + rowL[it]) * K + qL[it];
        aOff[it] = sbase + (uint32_t)(rowL[it] * 36 + qL[it]) * 4;
        bOff[it] = aOff[it] + 4608 * 4;
    }

    const int NT = K >> 5;
#pragma unroll
    for (int it = 0; it < 4; it++) {
        cp_async16(aOff[it], aPtr[it]);
        cp_async16(bOff[it], bPtr[it]);
    }
    CP_COMMIT();

    for (int kt = 0; kt < NT; kt++) {
        int buf = kt & 1;
        CP_WAIT_ALL();
        __syncthreads();
        if (kt + 1 < NT) {
            int kb = (kt + 1) << 5;
            uint32_t boff = (kt + 1) & 1 ? 9216u * 4u : 0u;
#pragma unroll
            for (int it = 0; it < 4; it++) {
                cp_async16(aOff[it] + boff, aPtr[it] + kb);
                cp_async16(bOff[it] + boff, bPtr[it] + kb);
            }
            CP_COMMIT();
        }

        const uint32_t* Ab = dynsm + (buf ? 9216 : 0);
        const uint32_t* Bb = Ab + 4608;
#pragma unroll
        for (int kf = 0; kf < 4; kf++) {
            int kc = kf << 3;
            uint32_t af[4][4], bf[4][2];
#pragma unroll
            for (int mi = 0; mi < 4; mi++) {
                int row = (wm << 6) + (mi << 4) + g;
                af[mi][0] = Ab[row * 36 + kc + t4];
                af[mi][1] = Ab[(row + 8) * 36 + kc + t4];
                af[mi][2] = Ab[row * 36 + kc + t4 + 4];
                af[mi][3] = Ab[(row + 8) * 36 + kc + t4 + 4];
            }
#pragma unroll
            for (int ni = 0; ni < 4; ni++) {
                int nr = (wn << 5) + (ni << 3) + g;
                bf[ni][0] = Bb[nr * 36 + kc + t4];
                bf[ni][1] = Bb[nr * 36 + kc + t4 + 4];
            }
#pragma unroll
            for (int mi = 0; mi < 4; mi++)
#pragma unroll
                for (int ni = 0; ni < 4; ni++)
                    mma_tf32(acc[mi][ni], af[mi], bf[ni]);
        }
    }

#pragma unroll
    for (int mi = 0; mi < 4; mi++) {
        int row0 = m0 + (wm << 6) + (mi << 4) + g;
#pragma unroll
        for (int ni = 0; ni < 4; ni++) {
            int col = n0 + (wn << 5) + (ni << 3) + (t4 << 1);
            float b0 = bias[col], b1 = bias[col + 1];
#pragma unroll
            for (int half = 0; half < 2; half++) {
                int row = row0 + half * 8;
                float v0 = acc[mi][ni][half * 2 + 0] + b0;
                float v1 = acc[mi][ni][half * 2 + 1] + b1;
                if (act == 1) {
                    v0 = 0.5f * v0 * (1.0f + erff(v0 * 0.70710678118654752f));
                    v1 = 0.5f * v1 * (1.0f + erff(v1 * 0.70710678118654752f));
                }
                if (act) {
                    v0 = roundtf(v0);
                    v1 = roundtf(v1);
                }
                float2 st = make_float2(v0, v1);
                *(float2*)(C + (size_t)row * N + col) = st;
            }
        }
    }
}

__global__ __launch_bounds__(256, 2) void gemm_mma_kernel(
    const float* __restrict__ A, const float* __restrict__ Bt,
    const float* __restrict__ bias, float* __restrict__ C,
    int M, int N, int K, int act) {
    extern __shared__ uint32_t dynsm[];
    gemm_body(A, Bt, bias, C, M, N, K, act, dynsm);
}

__global__ __launch_bounds__(256, 2) void qkv_gemm_kernel(
    const float* __restrict__ lnbase, const float* __restrict__ wtbase,
    const float* __restrict__ bq, const float* __restrict__ bk,
    const float* __restrict__ bv, float* __restrict__ outbase) {
    extern __shared__ uint32_t dynsm[];
    int z = blockIdx.z;
    const float* bias = (z == 0) ? bq : ((z == 1) ? bk : bv);
    gemm_body(lnbase + (size_t)z * 3145728, wtbase + (size_t)z * 589824,
              bias, outbase + (size_t)z * 3145728, 4096, 768, 768, 2, dynsm);
}

// =========================================================================
// flash attention: 128-row Q tiles, 256 threads (R13 geometry)
// W (wmap) read via registers (no smem stage; validated in R14)
// dyn smem (u32 words):
//   Qs [128][68] @ 0       KS [2][64][68] @ 8704   VS [2][64][72] @ 17408
//   Ps [128][68] @ 26624   -> total 35328 words = 141312 B
// =========================================================================
__global__ __launch_bounds__(256) void attn_mma_kernel(
    const float* __restrict__ q, const float* __restrict__ k,
    const float* __restrict__ v, const float* __restrict__ wm,
    float* __restrict__ att_out) {
    extern __shared__ uint32_t dynsm[];
    uint32_t (*Qs)[68] = (uint32_t(*)[68])(dynsm);
    const uint32_t* KSu = dynsm + 8704;
    const uint32_t* VSu = dynsm + 17408;
    uint32_t (*Ps)[68] = (uint32_t(*)[68])(dynsm + 26624);

    uint32_t sbase = smem_u32(dynsm);
    uint32_t kByte = sbase + 8704u * 4u;
    uint32_t vByte = sbase + 17408u * 4u;

    int bh = blockIdx.y;
    int b = bh / 12, h = bh - b * 12;
    int q0 = blockIdx.x << 7;
    int tid = threadIdx.x;
    int lane = tid & 31, warp = tid >> 5;
    int g = lane >> 2, t4 = lane & 3;
    int r = (warp << 4) + g;

#pragma unroll
    for (int it = 0; it < 8; it++) {
        int e = (it << 8) + tid;
        int row = e >> 4, c4 = (e & 15) << 2;
        float4 qv = *(const float4*)(q + (size_t)(b * 1024 + q0 + row) * 768 + h * 64 + c4);
        Qs[row][c4 + 0] = __float_as_uint(qv.x * 0.125f);
        Qs[row][c4 + 1] = __float_as_uint(qv.y * 0.125f);
        Qs[row][c4 + 2] = __float_as_uint(qv.z * 0.125f);
        Qs[row][c4 + 3] = __float_as_uint(qv.w * 0.125f);
    }

    const float* wbase = wm + ((size_t)(b * 12) << 20);

#define LOAD_TILES(bsel, k0)                                                            \
    do {                                                                                \
        uint32_t kb_ = kByte + (uint32_t)(bsel) * 17408u;                               \
        uint32_t vb_ = vByte + (uint32_t)(bsel) * 18432u;                               \
        _Pragma("unroll")                                                               \
        for (int it_ = 0; it_ < 4; it_++) {                                             \
            int e_ = (it_ << 8) + tid;                                                  \
            int row_ = e_ >> 4, c4_ = (e_ & 15) << 2;                                   \
            size_t ga_ = (size_t)(b * 1024 + (k0) + row_) * 768 + h * 64 + c4_;         \
            cp_async16(kb_ + (uint32_t)((row_ * 68 + c4_) << 2), k + ga_);              \
            cp_async16(vb_ + (uint32_t)((row_ * 72 + c4_) << 2), v + ga_);              \
        }                                                                               \
        CP_COMMIT();                                                                    \
    } while (0)

    float of[8][4];
#pragma unroll
    for (int ni = 0; ni < 8; ni++)
#pragma unroll
        for (int j = 0; j < 4; j++) of[ni][j] = 0.f;
    float lrun_a = 0.f, lrun_b = 0.f;

    LOAD_TILES(0, 0);

    for (int kt = 0; kt < 16; kt++) {
        int buf = kt & 1;
        int k0 = kt << 6;
        CP_WAIT_ALL();
        __syncthreads();
        if (kt + 1 < 16) LOAD_TILES((kt + 1) & 1, (kt + 1) << 6);

        // W fragment via coalesced LDG.64 (hides under the MMA loop below)
        float wreg[8][4];
        {
            const float* wr0 = wbase + (size_t)(q0 + r) * 1024 + k0;
            const float* wr1 = wr0 + (size_t)8 * 1024;
#pragma unroll
            for (int ni = 0; ni < 8; ni++) {
                int c0 = (ni << 3) + (t4 << 1);
                float2 wa = *(const float2*)(wr0 + c0);
                float2 wb = *(const float2*)(wr1 + c0);
                wreg[ni][0] = wa.x;
                wreg[ni][1] = wa.y;
                wreg[ni][2] = wb.x;
                wreg[ni][3] = wb.y;
            }
        }

        const uint32_t* Kb = KSu + buf * 4352;
        const uint32_t* Vb = VSu + buf * 4608;

        // S = Q @ K^T
        float sacc[8][4];
#pragma unroll
        for (int ni = 0; ni < 8; ni++)
#pragma unroll
            for (int j = 0; j < 4; j++) sacc[ni][j] = 0.f;
#pragma unroll
        for (int kf = 0; kf < 8; kf++) {
            int kc = kf << 3;
            uint32_t A[4];
            A[0] = Qs[r][kc + t4];
            A[1] = Qs[r + 8][kc + t4];
            A[2] = Qs[r][kc + t4 + 4];
            A[3] = Qs[r + 8][kc + t4 + 4];
#pragma unroll
            for (int ni = 0; ni < 8; ni++) {
                const uint32_t* krow = Kb + ((ni << 3) + g) * 68;
                uint32_t B[2];
                B[0] = krow[kc + t4];
                B[1] = krow[kc + t4 + 4];
                mma_tf32(sacc[ni], A, B);
            }
        }

        // wmap multiply + exp (scores bounded; no max needed)
        float sum_a = 0.f, sum_b = 0.f;
#pragma unroll
        for (int ni = 0; ni < 8; ni++) {
            int c0 = (ni << 3) + (t4 << 1);
            float p0 = __expf(sacc[ni][0] * wreg[ni][0]);
            float p1 = __expf(sacc[ni][1] * wreg[ni][1]);
            float p2 = __expf(sacc[ni][2] * wreg[ni][2]);
            float p3 = __expf(sacc[ni][3] * wreg[ni][3]);
            sum_a += p0 + p1;
            sum_b += p2 + p3;
            Ps[r][c0] = f2tf32(p0);
            Ps[r][c0 + 1] = f2tf32(p1);
            Ps[r + 8][c0] = f2tf32(p2);
            Ps[r + 8][c0 + 1] = f2tf32(p3);
        }
        sum_a += __shfl_xor_sync(0xffffffffu, sum_a, 1);
        sum_a += __shfl_xor_sync(0xffffffffu, sum_a, 2);
        sum_b += __shfl_xor_sync(0xffffffffu, sum_b, 1);
        sum_b += __shfl_xor_sync(0xffffffffu, sum_b, 2);
        lrun_a += sum_a;
        lrun_b += sum_b;

        __syncwarp();

        // O += P @ V
#pragma unroll
        for (int kf = 0; kf < 8; kf++) {
            int kc = kf << 3;
            uint32_t A[4];
            A[0] = Ps[r][kc + t4];
            A[1] = Ps[r + 8][kc + t4];
            A[2] = Ps[r][kc + t4 + 4];
            A[3] = Ps[r + 8][kc + t4 + 4];
            const uint32_t* v0r = Vb + (kc + t4) * 72;
            const uint32_t* v1r = Vb + (kc + t4 + 4) * 72;
#pragma unroll
            for (int ni = 0; ni < 8; ni++) {
                int d = (ni << 3) + g;
                uint32_t B[2];
                B[0] = v0r[d];
                B[1] = v1r[d];
                mma_tf32(of[ni], A, B);
            }
        }
    }

    float ia = 1.0f / lrun_a, ib = 1.0f / lrun_b;
#pragma unroll
    for (int ni = 0; ni < 8; ni++) {
        int col = h * 64 + (ni << 3) + (t4 << 1);
        float2 oa = make_float2(roundtf(of[ni][0] * ia), roundtf(of[ni][1] * ia));
        float2 ob = make_float2(roundtf(of[ni][2] * ib), roundtf(of[ni][3] * ib));
        *(float2*)(att_out + (size_t)(b * 1024 + q0 + r) * 768 + col) = oa;
        *(float2*)(att_out + (size_t)(b * 1024 + q0 + r + 8) * 768 + col) = ob;
    }
#undef LOAD_TILES
}

// =========================================================================
// epipolar parameter setup (unchanged)
// =========================================================================
__global__ void setup_params_kernel(const float* __restrict__ intr,
                                    const float* __restrict__ c2w) {
    int t = threadIdx.x;
    if (t >= 8) return;
    int dir = t >> 2, b = t & 3;

    float k3[3][3];
    const float Wf = 32.0f * 16.0f / 9.0f;
    for (int i = 0; i < 3; i++)
        for (int j = 0; j < 3; j++)
            k3[i][j] = intr[b * 16 + i * 4 + j];
    for (int j = 0; j < 3; j++) { k3[0][j] *= Wf; k3[1][j] *= 32.0f; }
    k3[0][2] = 16.0f; k3[1][2] = 16.0f;

    int si = (dir == 0) ? 1 : 0;
    int ti = (dir == 0) ? 0 : 1;
    const float* S = c2w + (si * 4 + b) * 16;
    const float* T = c2w + (ti * 4 + b) * 16;
    float sr[3][3], st[3], tr[3][3], tt[3];
    for (int i = 0; i < 3; i++) {
        for (int j = 0; j < 3; j++) { sr[i][j] = S[i * 4 + j]; tr[i][j] = T[i * 4 + j]; }
        st[i] = S[i * 4 + 3]; tt[i] = T[i * 4 + 3];
    }
    float det = tr[0][0] * (tr[1][1] * tr[2][2] - tr[1][2] * tr[2][1])
              - tr[0][1] * (tr[1][0] * tr[2][2] - tr[1][2] * tr[2][0])
              + tr[0][2] * (tr[1][0] * tr[2][1] - tr[1][1] * tr[2][0]);
    float id = 1.0f / det;
    float ti3[3][3];
    ti3[0][0] = (tr[1][1] * tr[2][2] - tr[1][2] * tr[2][1]) * id;
    ti3[0][1] = (tr[0][2] * tr[2][1] - tr[0][1] * tr[2][2]) * id;
    ti3[0][2] = (tr[0][1] * tr[1][2] - tr[0][2] * tr[1][1]) * id;
    ti3[1][0] = (tr[1][2] * tr[2][0] - tr[1][0] * tr[2][2]) * id;
    ti3[1][1] = (tr[0][0] * tr[2][2] - tr[0][2] * tr[2][0]) * id;
    ti3[1][2] = (tr[0][2] * tr[1][0] - tr[0][0] * tr[1][2]) * id;
    ti3[2][0] = (tr[1][0] * tr[2][1] - tr[1][1] * tr[2][0]) * id;
    ti3[2][1] = (tr[0][1] * tr[2][0] - tr[0][0] * tr[2][1]) * id;
    ti3[2][2] = (tr[0][0] * tr[1][1] - tr[0][1] * tr[1][0]) * id;

    float TR[3][3], Mm[3][3];
    for (int i = 0; i < 3; i++)
        for (int j = 0; j < 3; j++) {
            float s = 0.f;
            for (int kk = 0; kk < 3; kk++) s += ti3[i][kk] * sr[kk][j];
            TR[i][j] = s;
        }
    for (int i = 0; i < 3; i++)
        for (int j = 0; j < 3; j++) {
            float s = 0.f;
            for (int kk = 0; kk < 3; kk++) s += k3[i][kk] * TR[kk][j];
            Mm[i][j] = s;
        }
    float o2[3], tv[3];
    for (int i = 0; i < 3; i++) {
        float s = 0.f;
        for (int kk = 0; kk < 3; kk++) s += ti3[i][kk] * st[kk];
        o2[i] = s - tt[i];
    }
    for (int i = 0; i < 3; i++) {
        float s = 0.f;
        for (int kk = 0; kk < 3; kk++) s += k3[i][kk] * o2[kk];
        tv[i] = s;
    }
    float* P = g_params[t];
    P[0] = Mm[0][0]; P[1] = Mm[0][1]; P[2] = Mm[0][2];
    P[3] = Mm[1][0]; P[4] = Mm[1][1]; P[5] = Mm[1][2];
    P[6] = Mm[2][0]; P[7] = Mm[2][1]; P[8] = Mm[2][2];
    P[9] = tv[0]; P[10] = tv[1]; P[11] = tv[2];
    P[12] = k3[0][0]; P[13] = k3[1][1]; P[14] = k3[0][2]; P[15] = k3[1][2];
}

// =========================================================================
// epipolar rows — band-skip fast-math (unchanged)
// =========================================================================
__global__ void epipolar_kernel(float* __restrict__ ep) {
    int i = blockIdx.x, b = blockIdx.y, dir = blockIdx.z;
    const float* P = g_params[dir * 4 + b];
    float M0 = P[0], M1 = P[1], M2 = P[2], M3 = P[3], M4 = P[4], M5 = P[5],
          M6 = P[6], M7 = P[7], M8 = P[8];
    float tv0 = P[9], tv1 = P[10], tv2 = P[11];
    float fx = P[12], fy = P[13], cx = P[14], cy = P[15];

    float ncx = ((float)(i & 31) - cx) / fx;
    float ncy = ((float)(i >> 5) - cy) / fy;
    float pux = M0 * ncx + M1 * ncy + M2 + tv0;
    float puy = M3 * ncx + M4 * ncy + M5 + tv1;
    float puz = M6 * ncx + M7 * ncy + M8 + tv2;
    float invz = 1.0f / (puz + 1e-6f);
    float px = pux * invz, py = puy * invz, pz = puz * invz;
    float ozi = 1.0f / tv2;
    float ox = tv0 * ozi, oy = tv1 * ozi, oz = tv2 * ozi;
    float ax = px - ox, ay = py - oy, az = pz - oz;
    float vlen2 = ax * ax + ay * ay + az * az;
    float inv_vlen = fast_rsqrt(vlen2);
    float inv_vlen2 = inv_vlen * inv_vlen;
    float bz = 1.0f - oz;

    const float C1 = 72.13475204444817f;
    const float C0 = -36.067376022224085f;
    const float HI2 = 0.85f * 0.85f;
    const float LO2 = 0.15f * 0.15f;

    int tid = threadIdx.x;
    float dwv[4];
    float lmax = -1e30f;
#pragma unroll
    for (int it = 0; it < 4; it++) {
        int j = tid + it * 256;
        float bx = (float)(j & 31) - ox;
        float by = (float)(j >> 5) - oy;
        float crx = ay * bz - az * by;
        float cry = az * bx - ax * bz;
        float crz = ax * by - ay * bx;
        float a2 = crx * crx + cry * cry + crz * crz;
        float d2 = a2 * inv_vlen2;
        float dw;
        if (d2 >= HI2) {
            dw = 0.0f;
        } else if (d2 <= LO2) {
            dw = 1.0f;
        } else {
            float dist = fast_sqrt(a2) * inv_vlen;
            float e = fast_ex2(C1 * dist + C0);
            dw = fast_rcp(1.0f + e);
        }
        dwv[it] = dw;
        lmax = fmaxf(lmax, dw);
    }
    __shared__ float red[256];
    red[tid] = lmax;
    __syncthreads();
    for (int s = 128; s > 0; s >>= 1) {
        if (tid < s) red[tid] = fmaxf(red[tid], red[tid + s]);
        __syncthreads();
    }
    float rmax = red[0];
    float* dst = ep + ((size_t)((dir * 4 + b) * 1024 + i) << 10);
#pragma unroll
    for (int it = 0; it < 4; it++) {
        int j = tid + it * 256;
        dst[j] = (rmax < 0.5f) ? 1.0f : dwv[it];
    }
}

// =========================================================================
// wmap: float4, streaming stores for broadcast planes (h>=1)
// =========================================================================
__global__ void wmap_kernel(const float* __restrict__ ep,
                            float* __restrict__ out_wm) {
    int b = blockIdx.z;
    int I0 = blockIdx.y << 5, J0 = blockIdx.x << 5;
    int tid = threadIdx.x;
    __shared__ float s1[32][33];
    const float* e0 = ep + ((size_t)(b * 1024) << 10);
    const float* e1 = ep + ((size_t)((4 + b) * 1024) << 10);

    {
        int j = tid >> 3, i4 = (tid & 7) << 2;
        float4 vv = *(const float4*)(e1 + (size_t)(J0 + j) * 1024 + I0 + i4);
        s1[j][i4 + 0] = vv.x;
        s1[j][i4 + 1] = vv.y;
        s1[j][i4 + 2] = vv.z;
        s1[j][i4 + 3] = vv.w;
    }
    __syncthreads();

    int i = tid >> 3, jq = (tid & 7) << 2;
    float4 a = *(const float4*)(e0 + (size_t)(I0 + i) * 1024 + J0 + jq);
    float4 w;
    w.x = a.x * s1[jq + 0][i];
    w.y = a.y * s1[jq + 1][i];
    w.z = a.z * s1[jq + 2][i];
    w.w = a.w * s1[jq + 3][i];
    size_t off = (size_t)(I0 + i) * 1024 + J0 + jq;
    float* dst = out_wm + (((size_t)(b * 12)) << 20) + off;
    *(float4*)dst = w;  // head-0 plane: normal store (read by attention)
#pragma unroll
    for (int h = 1; h < 12; h++)
        st_cs_f4(dst + ((size_t)h << 20), w);  // evict-first
}

// =========================================================================
// layernorm body + wrappers (unchanged)
// =========================================================================
__device__ __forceinline__ void ln_body(const float* __restrict__ in,
                                        const float* __restrict__ res,
                                        const float* __restrict__ gam,
                                        const float* __restrict__ bet,
                                        float* __restrict__ out, int rnd) {
    int row = (blockIdx.x << 3) + (threadIdx.x >> 5);
    int lane = threadIdx.x & 31;
    const float* p = in + (size_t)row * 768;
    float v[24];
    float s = 0.f;
#pragma unroll
    for (int it = 0; it < 24; it++) {
        int c = lane + (it << 5);
        v[it] = p[c];
        if (res) v[it] += res[(size_t)row * 768 + c];
        s += v[it];
    }
#pragma unroll
    for (int o = 16; o > 0; o >>= 1) s += __shfl_xor_sync(0xffffffffu, s, o);
    float mu = s * (1.0f / 768.0f);
    float qsum = 0.f;
#pragma unroll
    for (int it = 0; it < 24; it++) {
        float d = v[it] - mu;
        qsum += d * d;
    }
#pragma unroll
    for (int o = 16; o > 0; o >>= 1) qsum += __shfl_xor_sync(0xffffffffu, qsum, o);
    float rstd = rsqrtf(qsum * (1.0f / 768.0f) + 1e-5f);
#pragma unroll
    for (int it = 0; it < 24; it++) {
        int c = lane + (it << 5);
        float val = (v[it] - mu) * rstd * gam[c] + bet[c];
        if (rnd) val = roundtf(val);
        out[(size_t)row * 768 + c] = val;
    }
}

__global__ void ln_kernel(const float* __restrict__ in, const float* __restrict__ res,
                          const float* __restrict__ gam, const float* __restrict__ bet,
                          float* __restrict__ out, int rnd) {
    ln_body(in, res, gam, bet, out, rnd);
}

__global__ void ln3_kernel(const float* __restrict__ x, const float* __restrict__ src,
                           const float* __restrict__ gq, const float* __restrict__ bq,
                           const float* __restrict__ gk, const float* __restrict__ bk,
                           const float* __restrict__ gv, const float* __restrict__ bv,
                           float* __restrict__ outbase) {
    int z = blockIdx.y;
    const float* in = (z == 0) ? x : src;
    const float* gam = (z == 0) ? gq : ((z == 1) ? gk : gv);
    const float* bet = (z == 0) ? bq : ((z == 1) ? bk : bv);
    ln_body(in, nullptr, gam, bet, outbase + (size_t)z * 3145728, 1);
}

// =========================================================================
// launch
// =========================================================================
extern "C" void kernel_launch(void* const* d_in, const int* in_sizes, int n_in,
                              void* d_out, int out_size) {
    const float* x      = (const float*)d_in[0];
    const float* src    = (const float*)d_in[1];
    const float* intr   = (const float*)d_in[2];
    const float* c2w    = (const float*)d_in[3];
    const float* lnq_g  = (const float*)d_in[4];
    const float* lnq_b  = (const float*)d_in[5];
    const float* Wq     = (const float*)d_in[6];
    const float* bq     = (const float*)d_in[7];
    const float* lnk_g  = (const float*)d_in[8];
    const float* lnk_b  = (const float*)d_in[9];
    const float* Wk     = (const float*)d_in[10];
    const float* bk     = (const float*)d_in[11];
    const float* lnv_g  = (const float*)d_in[12];
    const float* lnv_b  = (const float*)d_in[13];
    const float* Wv     = (const float*)d_in[14];
    const float* bv     = (const float*)d_in[15];
    const float* Wp     = (const float*)d_in[16];
    const float* bp     = (const float*)d_in[17];
    const float* pre_g  = (const float*)d_in[18];
    const float* pre_b  = (const float*)d_in[19];
    const float* W1     = (const float*)d_in[20];
    const float* b1     = (const float*)d_in[21];
    const float* W2     = (const float*)d_in[22];
    const float* b2     = (const float*)d_in[23];
    const float* post_g = (const float*)d_in[24];
    const float* post_b = (const float*)d_in[25];

    float* out_z  = (float*)d_out;
    float* out_wm = out_z + (size_t)4 * 1024 * 768;

    void* sp = nullptr;
    cudaGetSymbolAddress(&sp, g_scratch);
    float* base = (float*)sp;
    float* ep  = base + OFF_EP;
    float* lnx = base + OFF_LNX;
    float* qb  = base + OFF_Q;
    float* kb  = qb + 3145728;
    float* vb  = kb + 3145728;
    float* att = base + OFF_ATT;
    float* p0  = base + OFF_P0;
    float* z0  = base + OFF_Z0;
    float* hid = base + OFF_HID;
    float* wqt = base + OFF_WQT;
    float* wkt = wqt + 589824;
    float* wvt = wkt + 589824;
    float* wpt = base + OFF_WPT;
    float* w1t = base + OFF_W1T;
    float* w2t = base + OFF_W2T;

    cudaFuncSetAttribute(attn_mma_kernel,
                         cudaFuncAttributeMaxDynamicSharedMemorySize, 141312);
    cudaFuncSetAttribute(gemm_mma_kernel,
                         cudaFuncAttributeMaxDynamicSharedMemorySize, 73728);
    cudaFuncSetAttribute(qkv_gemm_kernel,
                         cudaFuncAttributeMaxDynamicSharedMemorySize, 73728);

    dim3 tb(32, 32);
    transpose_all_kernel<<<4608, tb>>>(Wq, Wk, Wv, Wp, W1, W2,
                                       wqt, wkt, wvt, wpt, w1t, w2t);

    setup_params_kernel<<<1, 8>>>(intr, c2w);
    epipolar_kernel<<<dim3(1024, 4, 2), 256>>>(ep);
    wmap_kernel<<<dim3(32, 32, 4), 256>>>(ep, out_wm);

    ln3_kernel<<<dim3(512, 3), 256>>>(x, src, lnq_g, lnq_b, lnk_g, lnk_b,
                                      lnv_g, lnv_b, lnx);

    qkv_gemm_kernel<<<dim3(6, 32, 3), 256, 73728>>>(lnx, wqt, bq, bk, bv, qb);

    attn_mma_kernel<<<dim3(8, 48), 256, 141312>>>(qb, kb, vb, out_wm, att);

    gemm_mma_kernel<<<dim3(6, 32), 256, 73728>>>(att, wpt, bp, p0, 4096, 768, 768, 0);
    ln_kernel<<<512, 256>>>(p0, nullptr, pre_g, pre_b, z0, 1);
    gemm_mma_kernel<<<dim3(12, 32), 256, 73728>>>(z0, w1t, b1, hid, 4096, 1536, 768, 1);
    gemm_mma_kernel<<<dim3(6, 32), 256, 73728>>>(hid, w2t, b2, p0, 4096, 768, 1536, 0);
    ln_kernel<<<512, 256>>>(p0, z0, post_g, post_b, out_z, 0);
}

// round 16
// speedup vs baseline: 1.0648x; 1.0648x over previous
#include <cuda_runtime.h>
#include <math.h>
#include <stdint.h>

// ---------------- static scratch ----------------
__device__ float g_scratch[51904512];
__device__ float g_params[8][16];

static const size_t OFF_EP   = 0;
static const size_t OFF_LNX  = 12582912;
static const size_t OFF_Q    = 22020096;
static const size_t OFF_ATT  = 31457280;
static const size_t OFF_P0   = 34603008;
static const size_t OFF_Z0   = 37748736;
static const size_t OFF_HID  = 40894464;
static const size_t OFF_WQT  = 47185920;
static const size_t OFF_WPT  = 48955392;
static const size_t OFF_W1T  = 49545216;
static const size_t OFF_W2T  = 50724864;

// =========================================================================
// helpers
// =========================================================================
__device__ __forceinline__ uint32_t f2tf32(float f) {
    uint32_t u;
    asm("cvt.rna.tf32.f32 %0, %1;" : "=r"(u) : "f"(f));
    return u;
}
__device__ __forceinline__ float roundtf(float f) {
    return __uint_as_float(f2tf32(f));
}

__device__ __forceinline__ void mma_tf32(float d[4], const uint32_t a[4], const uint32_t b[2]) {
    asm volatile(
        "mma.sync.aligned.m16n8k8.row.col.f32.tf32.tf32.f32 "
        "{%0,%1,%2,%3}, {%4,%5,%6,%7}, {%8,%9}, {%0,%1,%2,%3};"
        : "+f"(d[0]), "+f"(d[1]), "+f"(d[2]), "+f"(d[3])
        : "r"(a[0]), "r"(a[1]), "r"(a[2]), "r"(a[3]), "r"(b[0]), "r"(b[1]));
}

__device__ __forceinline__ uint32_t smem_u32(const void* p) {
    uint32_t a;
    asm("{ .reg .u64 t; cvta.to.shared.u64 t, %1; cvt.u32.u64 %0, t; }" : "=r"(a) : "l"(p));
    return a;
}
__device__ __forceinline__ void cp_async16(uint32_t dst, const void* src) {
    asm volatile("cp.async.cg.shared.global [%0], [%1], 16;" :: "r"(dst), "l"(src));
}
#define CP_COMMIT() asm volatile("cp.async.commit_group;" ::: "memory")
#define CP_WAIT0() asm volatile("cp.async.wait_group 0;" ::: "memory")
#define CP_WAIT1() asm volatile("cp.async.wait_group 1;" ::: "memory")

__device__ __forceinline__ float fast_sqrt(float x)  { float r; asm("sqrt.approx.f32 %0, %1;"  : "=f"(r) : "f"(x)); return r; }
__device__ __forceinline__ float fast_rsqrt(float x) { float r; asm("rsqrt.approx.f32 %0, %1;" : "=f"(r) : "f"(x)); return r; }
__device__ __forceinline__ float fast_rcp(float x)   { float r; asm("rcp.approx.f32 %0, %1;"   : "=f"(r) : "f"(x)); return r; }
__device__ __forceinline__ float fast_ex2(float x)   { float r; asm("ex2.approx.f32 %0, %1;"   : "=f"(r) : "f"(x)); return r; }

// =========================================================================
// merged weight transpose (unchanged)
// =========================================================================
__global__ void transpose_all_kernel(
    const float* __restrict__ Wq, const float* __restrict__ Wk,
    const float* __restrict__ Wv, const float* __restrict__ Wp,
    const float* __restrict__ W1, const float* __restrict__ W2,
    float* __restrict__ wqt, float* __restrict__ wkt,
    float* __restrict__ wvt, float* __restrict__ wpt,
    float* __restrict__ w1t, float* __restrict__ w2t) {
    __shared__ float t[32][33];
    int bid = blockIdx.x;
    const float* in;
    float* out;
    int R, C, tl;
    if (bid < 2304) {
        int seg = bid / 576;
        tl = bid - seg * 576;
        R = 768; C = 768;
        in  = (seg == 0) ? Wq  : (seg == 1) ? Wk  : (seg == 2) ? Wv  : Wp;
        out = (seg == 0) ? wqt : (seg == 1) ? wkt : (seg == 2) ? wvt : wpt;
    } else if (bid < 3456) {
        tl = bid - 2304;
        R = 768; C = 1536;
        in = W1; out = w1t;
    } else {
        tl = bid - 3456;
        R = 1536; C = 768;
        in = W2; out = w2t;
    }
    int tilesX = C >> 5;
    int c0 = (tl % tilesX) << 5, r0 = (tl / tilesX) << 5;
    int tx = threadIdx.x, ty = threadIdx.y;
    t[ty][tx] = in[(size_t)(r0 + ty) * C + c0 + tx];
    __syncthreads();
    out[(size_t)(c0 + ty) * R + r0 + tx] = roundtf(t[tx][ty]);
}

// =========================================================================
// 3-stage cp.async pipelined mma.sync tf32 GEMM body
// buffers: 3 x (As[128][36] + Bs[128][36]) = 3 x 9216 u32 = 110592 B
// act: 0 = none, 1 = gelu + tf32-round, 2 = tf32-round only
// =========================================================================
__device__ __forceinline__ void gemm_body(
    const float* __restrict__ A, const float* __restrict__ Bt,
    const float* __restrict__ bias, float* __restrict__ C,
    int M, int N, int K, int act, uint32_t* dynsm) {
    int tid = threadIdx.x;
    int lane = tid & 31, warp = tid >> 5;
    int wm = warp >> 2, wn = warp & 3;
    int g = lane >> 2, t4 = lane & 3;
    int m0 = blockIdx.y << 7, n0 = blockIdx.x << 7;

    float acc[4][4][4];
#pragma unroll
    for (int i = 0; i < 4; i++)
#pragma unroll
        for (int j = 0; j < 4; j++)
#pragma unroll
            for (int r = 0; r < 4; r++) acc[i][j][r] = 0.f;

    int rowL[4], qL[4];
#pragma unroll
    for (int it = 0; it < 4; it++) {
        int e = (it << 8) + tid;
        rowL[it] = e >> 3;
        qL[it] = (e & 7) << 2;
    }
    const float* aPtr[4];
    const float* bPtr[4];
    uint32_t aOff[4], bOff[4];
    uint32_t sbase = smem_u32(dynsm);
#pragma unroll
    for (int it = 0; it < 4; it++) {
        aPtr[it] = A + (size_t)(m0 + rowL[it]) * K + qL[it];
        bPtr[it] = Bt + (size_t)(n0 + rowL[it]) * K + qL[it];
        aOff[it] = sbase + (uint32_t)(rowL[it] * 36 + qL[it]) * 4;
        bOff[it] = aOff[it] + 4608 * 4;
    }

    const int NT = K >> 5;  // >= 2 always here (24 or 48)
    // preload stages 0 and 1
#pragma unroll
    for (int it = 0; it < 4; it++) {
        cp_async16(aOff[it], aPtr[it]);
        cp_async16(bOff[it], bPtr[it]);
    }
    CP_COMMIT();
#pragma unroll
    for (int it = 0; it < 4; it++) {
        cp_async16(aOff[it] + 9216u * 4u, aPtr[it] + 32);
        cp_async16(bOff[it] + 9216u * 4u, bPtr[it] + 32);
    }
    CP_COMMIT();

    int bufsel = 0;          // buffer of current kt
    int nextbuf = 2;         // buffer for kt+2
    for (int kt = 0; kt < NT; kt++) {
        if (kt + 1 < NT) CP_WAIT1(); else CP_WAIT0();  // loads(kt) complete
        __syncthreads();     // visible; all warps done with compute(kt-1)
        if (kt + 2 < NT) {   // refill the buffer freed by compute(kt-1)
            int kb = (kt + 2) << 5;
            uint32_t boff = (uint32_t)nextbuf * 9216u * 4u;
#pragma unroll
            for (int it = 0; it < 4; it++) {
                cp_async16(aOff[it] + boff, aPtr[it] + kb);
                cp_async16(bOff[it] + boff, bPtr[it] + kb);
            }
            CP_COMMIT();
        }

        const uint32_t* Ab = dynsm + bufsel * 9216;
        const uint32_t* Bb = Ab + 4608;
#pragma unroll
        for (int kf = 0; kf < 4; kf++) {
            int kc = kf << 3;
            uint32_t af[4][4], bf[4][2];
#pragma unroll
            for (int mi = 0; mi < 4; mi++) {
                int row = (wm << 6) + (mi << 4) + g;
                af[mi][0] = Ab[row * 36 + kc + t4];
                af[mi][1] = Ab[(row + 8) * 36 + kc + t4];
                af[mi][2] = Ab[row * 36 + kc + t4 + 4];
                af[mi][3] = Ab[(row + 8) * 36 + kc + t4 + 4];
            }
#pragma unroll
            for (int ni = 0; ni < 4; ni++) {
                int nr = (wn << 5) + (ni << 3) + g;
                bf[ni][0] = Bb[nr * 36 + kc + t4];
                bf[ni][1] = Bb[nr * 36 + kc + t4 + 4];
            }
#pragma unroll
            for (int mi = 0; mi < 4; mi++)
#pragma unroll
                for (int ni = 0; ni < 4; ni++)
                    mma_tf32(acc[mi][ni], af[mi], bf[ni]);
        }
        bufsel = (bufsel == 2) ? 0 : bufsel + 1;
        nextbuf = (nextbuf == 2) ? 0 : nextbuf + 1;
    }

#pragma unroll
    for (int mi = 0; mi < 4; mi++) {
        int row0 = m0 + (wm << 6) + (mi << 4) + g;
#pragma unroll
        for (int ni = 0; ni < 4; ni++) {
            int col = n0 + (wn << 5) + (ni << 3) + (t4 << 1);
            float b0 = bias[col], b1 = bias[col + 1];
#pragma unroll
            for (int half = 0; half < 2; half++) {
                int row = row0 + half * 8;
                float v0 = acc[mi][ni][half * 2 + 0] + b0;
                float v1 = acc[mi][ni][half * 2 + 1] + b1;
                if (act == 1) {
                    v0 = 0.5f * v0 * (1.0f + erff(v0 * 0.70710678118654752f));
                    v1 = 0.5f * v1 * (1.0f + erff(v1 * 0.70710678118654752f));
                }
                if (act) {
                    v0 = roundtf(v0);
                    v1 = roundtf(v1);
                }
                float2 st = make_float2(v0, v1);
                *(float2*)(C + (size_t)row * N + col) = st;
            }
        }
    }
}

__global__ __launch_bounds__(256, 2) void gemm_mma_kernel(
    const float* __restrict__ A, const float* __restrict__ Bt,
    const float* __restrict__ bias, float* __restrict__ C,
    int M, int N, int K, int act) {
    extern __shared__ uint32_t dynsm[];
    gemm_body(A, Bt, bias, C, M, N, K, act, dynsm);
}

__global__ __launch_bounds__(256, 2) void qkv_gemm_kernel(
    const float* __restrict__ lnbase, const float* __restrict__ wtbase,
    const float* __restrict__ bq, const float* __restrict__ bk,
    const float* __restrict__ bv, float* __restrict__ outbase) {
    extern __shared__ uint32_t dynsm[];
    int z = blockIdx.z;
    const float* bias = (z == 0) ? bq : ((z == 1) ? bk : bv);
    gemm_body(lnbase + (size_t)z * 3145728, wtbase + (size_t)z * 589824,
              bias, outbase + (size_t)z * 3145728, 4096, 768, 768, 2, dynsm);
}

// =========================================================================
// cp.async double-buffered flash attention (exact R13 version — best known)
// dyn smem (u32 words): Qs[128][68]@0 KS[2][64][68]@8704 VS[2][64][72]@17408
//   WS[2][128][68]@26624 Ps[128][68]@44032 -> 210944 B
// =========================================================================
__global__ __launch_bounds__(256) void attn_mma_kernel(
    const float* __restrict__ q, const float* __restrict__ k,
    const float* __restrict__ v, const float* __restrict__ wm,
    float* __restrict__ att_out) {
    extern __shared__ uint32_t dynsm[];
    uint32_t (*Qs)[68] = (uint32_t(*)[68])(dynsm);
    const uint32_t* KSu = dynsm + 8704;
    const uint32_t* VSu = dynsm + 17408;
    const float* WSf = (const float*)(dynsm + 26624);
    uint32_t (*Ps)[68] = (uint32_t(*)[68])(dynsm + 44032);

    uint32_t sbase = smem_u32(dynsm);
    uint32_t kByte = sbase + 8704u * 4u;
    uint32_t vByte = sbase + 17408u * 4u;
    uint32_t wByte = sbase + 26624u * 4u;

    int bh = blockIdx.y;
    int b = bh / 12, h = bh - b * 12;
    int q0 = blockIdx.x << 7;
    int tid = threadIdx.x;
    int lane = tid & 31, warp = tid >> 5;
    int g = lane >> 2, t4 = lane & 3;
    int r = (warp << 4) + g;

#pragma unroll
    for (int it = 0; it < 8; it++) {
        int e = (it << 8) + tid;
        int row = e >> 4, c4 = (e & 15) << 2;
        float4 qv = *(const float4*)(q + (size_t)(b * 1024 + q0 + row) * 768 + h * 64 + c4);
        Qs[row][c4 + 0] = __float_as_uint(qv.x * 0.125f);
        Qs[row][c4 + 1] = __float_as_uint(qv.y * 0.125f);
        Qs[row][c4 + 2] = __float_as_uint(qv.z * 0.125f);
        Qs[row][c4 + 3] = __float_as_uint(qv.w * 0.125f);
    }

    const float* wbase = wm + ((size_t)(b * 12) << 20);

#define LOAD_TILES(bsel, k0)                                                            \
    do {                                                                                \
        uint32_t kb_ = kByte + (uint32_t)(bsel) * 17408u;                               \
        uint32_t vb_ = vByte + (uint32_t)(bsel) * 18432u;                               \
        uint32_t wb_ = wByte + (uint32_t)(bsel) * 34816u;                               \
        _Pragma("unroll")                                                               \
        for (int it_ = 0; it_ < 4; it_++) {                                             \
            int e_ = (it_ << 8) + tid;                                                  \
            int row_ = e_ >> 4, c4_ = (e_ & 15) << 2;                                   \
            size_t ga_ = (size_t)(b * 1024 + (k0) + row_) * 768 + h * 64 + c4_;         \
            cp_async16(kb_ + (uint32_t)((row_ * 68 + c4_) << 2), k + ga_);              \
            cp_async16(vb_ + (uint32_t)((row_ * 72 + c4_) << 2), v + ga_);              \
        }                                                                               \
        _Pragma("unroll")                                                               \
        for (int it_ = 0; it_ < 8; it_++) {                                             \
            int e_ = (it_ << 8) + tid;                                                  \
            int row_ = e_ >> 4, c4_ = (e_ & 15) << 2;                                   \
            cp_async16(wb_ + (uint32_t)((row_ * 68 + c4_) << 2),                        \
                       wbase + (size_t)(q0 + row_) * 1024 + (k0) + c4_);                \
        }                                                                               \
        CP_COMMIT();                                                                    \
    } while (0)

    float of[8][4];
#pragma unroll
    for (int ni = 0; ni < 8; ni++)
#pragma unroll
        for (int j = 0; j < 4; j++) of[ni][j] = 0.f;
    float lrun_a = 0.f, lrun_b = 0.f;

    LOAD_TILES(0, 0);

    for (int kt = 0; kt < 16; kt++) {
        int buf = kt & 1;
        CP_WAIT0();
        __syncthreads();
        if (kt + 1 < 16) LOAD_TILES((kt + 1) & 1, (kt + 1) << 6);

        const uint32_t* Kb = KSu + buf * 4352;
        const uint32_t* Vb = VSu + buf * 4608;
        const float* Wb = WSf + buf * 8704;

        float sacc[8][4];
#pragma unroll
        for (int ni = 0; ni < 8; ni++)
#pragma unroll
            for (int j = 0; j < 4; j++) sacc[ni][j] = 0.f;
#pragma unroll
        for (int kf = 0; kf < 8; kf++) {
            int kc = kf << 3;
            uint32_t A[4];
            A[0] = Qs[r][kc + t4];
            A[1] = Qs[r + 8][kc + t4];
            A[2] = Qs[r][kc + t4 + 4];
            A[3] = Qs[r + 8][kc + t4 + 4];
#pragma unroll
            for (int ni = 0; ni < 8; ni++) {
                const uint32_t* krow = Kb + ((ni << 3) + g) * 68;
                uint32_t B[2];
                B[0] = krow[kc + t4];
                B[1] = krow[kc + t4 + 4];
                mma_tf32(sacc[ni], A, B);
            }
        }

        const float* wr0 = Wb + r * 68;
        const float* wr1 = Wb + (r + 8) * 68;
        float sum_a = 0.f, sum_b = 0.f;
#pragma unroll
        for (int ni = 0; ni < 8; ni++) {
            int c0 = (ni << 3) + (t4 << 1);
            float p0 = __expf(sacc[ni][0] * wr0[c0]);
            float p1 = __expf(sacc[ni][1] * wr0[c0 + 1]);
            float p2 = __expf(sacc[ni][2] * wr1[c0]);
            float p3 = __expf(sacc[ni][3] * wr1[c0 + 1]);
            sum_a += p0 + p1;
            sum_b += p2 + p3;
            Ps[r][c0] = f2tf32(p0);
            Ps[r][c0 + 1] = f2tf32(p1);
            Ps[r + 8][c0] = f2tf32(p2);
            Ps[r + 8][c0 + 1] = f2tf32(p3);
        }
        sum_a += __shfl_xor_sync(0xffffffffu, sum_a, 1);
        sum_a += __shfl_xor_sync(0xffffffffu, sum_a, 2);
        sum_b += __shfl_xor_sync(0xffffffffu, sum_b, 1);
        sum_b += __shfl_xor_sync(0xffffffffu, sum_b, 2);
        lrun_a += sum_a;
        lrun_b += sum_b;

        __syncwarp();

#pragma unroll
        for (int kf = 0; kf < 8; kf++) {
            int kc = kf << 3;
            uint32_t A[4];
            A[0] = Ps[r][kc + t4];
            A[1] = Ps[r + 8][kc + t4];
            A[2] = Ps[r][kc + t4 + 4];
            A[3] = Ps[r + 8][kc + t4 + 4];
            const uint32_t* v0r = Vb + (kc + t4) * 72;
            const uint32_t* v1r = Vb + (kc + t4 + 4) * 72;
#pragma unroll
            for (int ni = 0; ni < 8; ni++) {
                int d = (ni << 3) + g;
                uint32_t B[2];
                B[0] = v0r[d];
                B[1] = v1r[d];
                mma_tf32(of[ni], A, B);
            }
        }
    }

    float ia = 1.0f / lrun_a, ib = 1.0f / lrun_b;
#pragma unroll
    for (int ni = 0; ni < 8; ni++) {
        int col = h * 64 + (ni << 3) + (t4 << 1);
        float2 oa = make_float2(roundtf(of[ni][0] * ia), roundtf(of[ni][1] * ia));
        float2 ob = make_float2(roundtf(of[ni][2] * ib), roundtf(of[ni][3] * ib));
        *(float2*)(att_out + (size_t)(b * 1024 + q0 + r) * 768 + col) = oa;
        *(float2*)(att_out + (size_t)(b * 1024 + q0 + r + 8) * 768 + col) = ob;
    }
#undef LOAD_TILES
}

// =========================================================================
// epipolar parameter setup (unchanged)
// =========================================================================
__global__ void setup_params_kernel(const float* __restrict__ intr,
                                    const float* __restrict__ c2w) {
    int t = threadIdx.x;
    if (t >= 8) return;
    int dir = t >> 2, b = t & 3;

    float k3[3][3];
    const float Wf = 32.0f * 16.0f / 9.0f;
    for (int i = 0; i < 3; i++)
        for (int j = 0; j < 3; j++)
            k3[i][j] = intr[b * 16 + i * 4 + j];
    for (int j = 0; j < 3; j++) { k3[0][j] *= Wf; k3[1][j] *= 32.0f; }
    k3[0][2] = 16.0f; k3[1][2] = 16.0f;

    int si = (dir == 0) ? 1 : 0;
    int ti = (dir == 0) ? 0 : 1;
    const float* S = c2w + (si * 4 + b) * 16;
    const float* T = c2w + (ti * 4 + b) * 16;
    float sr[3][3], st[3], tr[3][3], tt[3];
    for (int i = 0; i < 3; i++) {
        for (int j = 0; j < 3; j++) { sr[i][j] = S[i * 4 + j]; tr[i][j] = T[i * 4 + j]; }
        st[i] = S[i * 4 + 3]; tt[i] = T[i * 4 + 3];
    }
    float det = tr[0][0] * (tr[1][1] * tr[2][2] - tr[1][2] * tr[2][1])
              - tr[0][1] * (tr[1][0] * tr[2][2] - tr[1][2] * tr[2][0])
              + tr[0][2] * (tr[1][0] * tr[2][1] - tr[1][1] * tr[2][0]);
    float id = 1.0f / det;
    float ti3[3][3];
    ti3[0][0] = (tr[1][1] * tr[2][2] - tr[1][2] * tr[2][1]) * id;
    ti3[0][1] = (tr[0][2] * tr[2][1] - tr[0][1] * tr[2][2]) * id;
    ti3[0][2] = (tr[0][1] * tr[1][2] - tr[0][2] * tr[1][1]) * id;
    ti3[1][0] = (tr[1][2] * tr[2][0] - tr[1][0] * tr[2][2]) * id;
    ti3[1][1] = (tr[0][0] * tr[2][2] - tr[0][2] * tr[2][0]) * id;
    ti3[1][2] = (tr[0][2] * tr[1][0] - tr[0][0] * tr[1][2]) * id;
    ti3[2][0] = (tr[1][0] * tr[2][1] - tr[1][1] * tr[2][0]) * id;
    ti3[2][1] = (tr[0][1] * tr[2][0] - tr[0][0] * tr[2][1]) * id;
    ti3[2][2] = (tr[0][0] * tr[1][1] - tr[0][1] * tr[1][0]) * id;

    float TR[3][3], Mm[3][3];
    for (int i = 0; i < 3; i++)
        for (int j = 0; j < 3; j++) {
            float s = 0.f;
            for (int kk = 0; kk < 3; kk++) s += ti3[i][kk] * sr[kk][j];
            TR[i][j] = s;
        }
    for (int i = 0; i < 3; i++)
        for (int j = 0; j < 3; j++) {
            float s = 0.f;
            for (int kk = 0; kk < 3; kk++) s += k3[i][kk] * TR[kk][j];
            Mm[i][j] = s;
        }
    float o2[3], tv[3];
    for (int i = 0; i < 3; i++) {
        float s = 0.f;
        for (int kk = 0; kk < 3; kk++) s += ti3[i][kk] * st[kk];
        o2[i] = s - tt[i];
    }
    for (int i = 0; i < 3; i++) {
        float s = 0.f;
        for (int kk = 0; kk < 3; kk++) s += k3[i][kk] * o2[kk];
        tv[i] = s;
    }
    float* P = g_params[t];
    P[0] = Mm[0][0]; P[1] = Mm[0][1]; P[2] = Mm[0][2];
    P[3] = Mm[1][0]; P[4] = Mm[1][1]; P[5] = Mm[1][2];
    P[6] = Mm[2][0]; P[7] = Mm[2][1]; P[8] = Mm[2][2];
    P[9] = tv[0]; P[10] = tv[1]; P[11] = tv[2];
    P[12] = k3[0][0]; P[13] = k3[1][1]; P[14] = k3[0][2]; P[15] = k3[1][2];
}

// =========================================================================
// epipolar rows — band-skip fast-math (unchanged)
// =========================================================================
__global__ void epipolar_kernel(float* __restrict__ ep) {
    int i = blockIdx.x, b = blockIdx.y, dir = blockIdx.z;
    const float* P = g_params[dir * 4 + b];
    float M0 = P[0], M1 = P[1], M2 = P[2], M3 = P[3], M4 = P[4], M5 = P[5],
          M6 = P[6], M7 = P[7], M8 = P[8];
    float tv0 = P[9], tv1 = P[10], tv2 = P[11];
    float fx = P[12], fy = P[13], cx = P[14], cy = P[15];

    float ncx = ((float)(i & 31) - cx) / fx;
    float ncy = ((float)(i >> 5) - cy) / fy;
    float pux = M0 * ncx + M1 * ncy + M2 + tv0;
    float puy = M3 * ncx + M4 * ncy + M5 + tv1;
    float puz = M6 * ncx + M7 * ncy + M8 + tv2;
    float invz = 1.0f / (puz + 1e-6f);
    float px = pux * invz, py = puy * invz, pz = puz * invz;
    float ozi = 1.0f / tv2;
    float ox = tv0 * ozi, oy = tv1 * ozi, oz = tv2 * ozi;
    float ax = px - ox, ay = py - oy, az = pz - oz;
    float vlen2 = ax * ax + ay * ay + az * az;
    float inv_vlen = fast_rsqrt(vlen2);
    float inv_vlen2 = inv_vlen * inv_vlen;
    float bz = 1.0f - oz;

    const float C1 = 72.13475204444817f;
    const float C0 = -36.067376022224085f;
    const float HI2 = 0.85f * 0.85f;
    const float LO2 = 0.15f * 0.15f;

    int tid = threadIdx.x;
    float dwv[4];
    float lmax = -1e30f;
#pragma unroll
    for (int it = 0; it < 4; it++) {
        int j = tid + it * 256;
        float bx = (float)(j & 31) - ox;
        float by = (float)(j >> 5) - oy;
        float crx = ay * bz - az * by;
        float cry = az * bx - ax * bz;
        float crz = ax * by - ay * bx;
        float a2 = crx * crx + cry * cry + crz * crz;
        float d2 = a2 * inv_vlen2;
        float dw;
        if (d2 >= HI2) {
            dw = 0.0f;
        } else if (d2 <= LO2) {
            dw = 1.0f;
        } else {
            float dist = fast_sqrt(a2) * inv_vlen;
            float e = fast_ex2(C1 * dist + C0);
            dw = fast_rcp(1.0f + e);
        }
        dwv[it] = dw;
        lmax = fmaxf(lmax, dw);
    }
    __shared__ float red[256];
    red[tid] = lmax;
    __syncthreads();
    for (int s = 128; s > 0; s >>= 1) {
        if (tid < s) red[tid] = fmaxf(red[tid], red[tid + s]);
        __syncthreads();
    }
    float rmax = red[0];
    float* dst = ep + ((size_t)((dir * 4 + b) * 1024 + i) << 10);
#pragma unroll
    for (int it = 0; it < 4; it++) {
        int j = tid + it * 256;
        dst[j] = (rmax < 0.5f) ? 1.0f : dwv[it];
    }
}

// =========================================================================
// wmap: float4-vectorized (exact R13 version)
// =========================================================================
__global__ void wmap_kernel(const float* __restrict__ ep,
                            float* __restrict__ out_wm) {
    int b = blockIdx.z;
    int I0 = blockIdx.y << 5, J0 = blockIdx.x << 5;
    int tid = threadIdx.x;
    __shared__ float s1[32][33];
    const float* e0 = ep + ((size_t)(b * 1024) << 10);
    const float* e1 = ep + ((size_t)((4 + b) * 1024) << 10);

    {
        int j = tid >> 3, i4 = (tid & 7) << 2;
        float4 vv = *(const float4*)(e1 + (size_t)(J0 + j) * 1024 + I0 + i4);
        s1[j][i4 + 0] = vv.x;
        s1[j][i4 + 1] = vv.y;
        s1[j][i4 + 2] = vv.z;
        s1[j][i4 + 3] = vv.w;
    }
    __syncthreads();

    int i = tid >> 3, jq = (tid & 7) << 2;
    float4 a = *(const float4*)(e0 + (size_t)(I0 + i) * 1024 + J0 + jq);
    float4 w;
    w.x = a.x * s1[jq + 0][i];
    w.y = a.y * s1[jq + 1][i];
    w.z = a.z * s1[jq + 2][i];
    w.w = a.w * s1[jq + 3][i];
    size_t off = (size_t)(I0 + i) * 1024 + J0 + jq;
    float* dst = out_wm + (((size_t)(b * 12)) << 20) + off;
#pragma unroll
    for (int h = 0; h < 12; h++)
        *(float4*)(dst + ((size_t)h << 20)) = w;
}

// =========================================================================
// layernorm body + wrappers (unchanged)
// =========================================================================
__device__ __forceinline__ void ln_body(const float* __restrict__ in,
                                        const float* __restrict__ res,
                                        const float* __restrict__ gam,
                                        const float* __restrict__ bet,
                                        float* __restrict__ out, int rnd) {
    int row = (blockIdx.x << 3) + (threadIdx.x >> 5);
    int lane = threadIdx.x & 31;
    const float* p = in + (size_t)row * 768;
    float v[24];
    float s = 0.f;
#pragma unroll
    for (int it = 0; it < 24; it++) {
        int c = lane + (it << 5);
        v[it] = p[c];
        if (res) v[it] += res[(size_t)row * 768 + c];
        s += v[it];
    }
#pragma unroll
    for (int o = 16; o > 0; o >>= 1) s += __shfl_xor_sync(0xffffffffu, s, o);
    float mu = s * (1.0f / 768.0f);
    float qsum = 0.f;
#pragma unroll
    for (int it = 0; it < 24; it++) {
        float d = v[it] - mu;
        qsum += d * d;
    }
#pragma unroll
    for (int o = 16; o > 0; o >>= 1) qsum += __shfl_xor_sync(0xffffffffu, qsum, o);
    float rstd = rsqrtf(qsum * (1.0f / 768.0f) + 1e-5f);
#pragma unroll
    for (int it = 0; it < 24; it++) {
        int c = lane + (it << 5);
        float val = (v[it] - mu) * rstd * gam[c] + bet[c];
        if (rnd) val = roundtf(val);
        out[(size_t)row * 768 + c] = val;
    }
}

__global__ void ln_kernel(const float* __restrict__ in, const float* __restrict__ res,
                          const float* __restrict__ gam, const float* __restrict__ bet,
                          float* __restrict__ out, int rnd) {
    ln_body(in, res, gam, bet, out, rnd);
}

__global__ void ln3_kernel(const float* __restrict__ x, const float* __restrict__ src,
                           const float* __restrict__ gq, const float* __restrict__ bq,
                           const float* __restrict__ gk, const float* __restrict__ bk,
                           const float* __restrict__ gv, const float* __restrict__ bv,
                           float* __restrict__ outbase) {
    int z = blockIdx.y;
    const float* in = (z == 0) ? x : src;
    const float* gam = (z == 0) ? gq : ((z == 1) ? gk : gv);
    const float* bet = (z == 0) ? bq : ((z == 1) ? bk : bv);
    ln_body(in, nullptr, gam, bet, outbase + (size_t)z * 3145728, 1);
}

// =========================================================================
// launch
// =========================================================================
extern "C" void kernel_launch(void* const* d_in, const int* in_sizes, int n_in,
                              void* d_out, int out_size) {
    const float* x      = (const float*)d_in[0];
    const float* src    = (const float*)d_in[1];
    const float* intr   = (const float*)d_in[2];
    const float* c2w    = (const float*)d_in[3];
    const float* lnq_g  = (const float*)d_in[4];
    const float* lnq_b  = (const float*)d_in[5];
    const float* Wq     = (const float*)d_in[6];
    const float* bq     = (const float*)d_in[7];
    const float* lnk_g  = (const float*)d_in[8];
    const float* lnk_b  = (const float*)d_in[9];
    const float* Wk     = (const float*)d_in[10];
    const float* bk     = (const float*)d_in[11];
    const float* lnv_g  = (const float*)d_in[12];
    const float* lnv_b  = (const float*)d_in[13];
    const float* Wv     = (const float*)d_in[14];
    const float* bv     = (const float*)d_in[15];
    const float* Wp     = (const float*)d_in[16];
    const float* bp     = (const float*)d_in[17];
    const float* pre_g  = (const float*)d_in[18];
    const float* pre_b  = (const float*)d_in[19];
    const float* W1     = (const float*)d_in[20];
    const float* b1     = (const float*)d_in[21];
    const float* W2     = (const float*)d_in[22];
    const float* b2     = (const float*)d_in[23];
    const float* post_g = (const float*)d_in[24];
    const float* post_b = (const float*)d_in[25];

    float* out_z  = (float*)d_out;
    float* out_wm = out_z + (size_t)4 * 1024 * 768;

    void* sp = nullptr;
    cudaGetSymbolAddress(&sp, g_scratch);
    float* base = (float*)sp;
    float* ep  = base + OFF_EP;
    float* lnx = base + OFF_LNX;
    float* qb  = base + OFF_Q;
    float* kb  = qb + 3145728;
    float* vb  = kb + 3145728;
    float* att = base + OFF_ATT;
    float* p0  = base + OFF_P0;
    float* z0  = base + OFF_Z0;
    float* hid = base + OFF_HID;
    float* wqt = base + OFF_WQT;
    float* wkt = wqt + 589824;
    float* wvt = wkt + 589824;
    float* wpt = base + OFF_WPT;
    float* w1t = base + OFF_W1T;
    float* w2t = base + OFF_W2T;

    cudaFuncSetAttribute(attn_mma_kernel,
                         cudaFuncAttributeMaxDynamicSharedMemorySize, 210944);
    cudaFuncSetAttribute(gemm_mma_kernel,
                         cudaFuncAttributeMaxDynamicSharedMemorySize, 110592);
    cudaFuncSetAttribute(qkv_gemm_kernel,
                         cudaFuncAttributeMaxDynamicSharedMemorySize, 110592);

    dim3 tb(32, 32);
    transpose_all_kernel<<<4608, tb>>>(Wq, Wk, Wv, Wp, W1, W2,
                                       wqt, wkt, wvt, wpt, w1t, w2t);

    setup_params_kernel<<<1, 8>>>(intr, c2w);
    epipolar_kernel<<<dim3(1024, 4, 2), 256>>>(ep);
    wmap_kernel<<<dim3(32, 32, 4), 256>>>(ep, out_wm);

    ln3_kernel<<<dim3(512, 3), 256>>>(x, src, lnq_g, lnq_b, lnk_g, lnk_b,
                                      lnv_g, lnv_b, lnx);

    qkv_gemm_kernel<<<dim3(6, 32, 3), 256, 110592>>>(lnx, wqt, bq, bk, bv, qb);

    attn_mma_kernel<<<dim3(8, 48), 256, 210944>>>(qb, kb, vb, out_wm, att);

    gemm_mma_kernel<<<dim3(6, 32), 256, 110592>>>(att, wpt, bp, p0, 4096, 768, 768, 0);
    ln_kernel<<<512, 256>>>(p0, nullptr, pre_g, pre_b, z0, 1);
    gemm_mma_kernel<<<dim3(12, 32), 256, 110592>>>(z0, w1t, b1, hid, 4096, 1536, 768, 1);
    gemm_mma_kernel<<<dim3(6, 32), 256, 110592>>>(hid, w2t, b2, p0, 4096, 768, 1536, 0);
    ln_kernel<<<512, 256>>>(p0, z0, post_g, post_b, out_z, 0);
}

// round 17
// speedup vs baseline: 1.1031x; 1.0360x over previous
#include <cuda_runtime.h>
#include <math.h>
#include <stdint.h>

// ---------------- static scratch ----------------
__device__ float g_scratch[51904512];
__device__ float g_params[8][16];

static const size_t OFF_EP   = 0;          // reused as z0_plain after wmap
static const size_t OFF_LNX  = 12582912;
static const size_t OFF_Q    = 22020096;
static const size_t OFF_ATT  = 31457280;
static const size_t OFF_P0   = 34603008;
static const size_t OFF_Z0   = 37748736;
static const size_t OFF_HID  = 40894464;
static const size_t OFF_WQT  = 47185920;
static const size_t OFF_WPT  = 48955392;
static const size_t OFF_W1T  = 49545216;
static const size_t OFF_W2T  = 50724864;

// ---------------- K-permutation: pos(c) within each 8-group ----------------
// pos(c8) = c8<4 ? 2*c8 : 2*(c8-4)+1   (so (t4, t4+4) land at (2t4, 2t4+1))
__device__ __forceinline__ int permP(int c) {
    return (c & ~7) | (((c & 3) << 1) | ((c >> 2) & 1));
}

// =========================================================================
// helpers
// =========================================================================
__device__ __forceinline__ uint32_t f2tf32(float f) {
    uint32_t u;
    asm("cvt.rna.tf32.f32 %0, %1;" : "=r"(u) : "f"(f));
    return u;
}
__device__ __forceinline__ float roundtf(float f) {
    return __uint_as_float(f2tf32(f));
}

__device__ __forceinline__ void mma_tf32(float d[4], const uint32_t a[4], const uint32_t b[2]) {
    asm volatile(
        "mma.sync.aligned.m16n8k8.row.col.f32.tf32.tf32.f32 "
        "{%0,%1,%2,%3}, {%4,%5,%6,%7}, {%8,%9}, {%0,%1,%2,%3};"
        : "+f"(d[0]), "+f"(d[1]), "+f"(d[2]), "+f"(d[3])
        : "r"(a[0]), "r"(a[1]), "r"(a[2]), "r"(a[3]), "r"(b[0]), "r"(b[1]));
}

__device__ __forceinline__ uint32_t smem_u32(const void* p) {
    uint32_t a;
    asm("{ .reg .u64 t; cvta.to.shared.u64 t, %1; cvt.u32.u64 %0, t; }" : "=r"(a) : "l"(p));
    return a;
}
__device__ __forceinline__ void cp_async16(uint32_t dst, const void* src) {
    asm volatile("cp.async.cg.shared.global [%0], [%1], 16;" :: "r"(dst), "l"(src));
}
#define CP_COMMIT() asm volatile("cp.async.commit_group;" ::: "memory")
#define CP_WAIT_ALL() asm volatile("cp.async.wait_group 0;" ::: "memory")

__device__ __forceinline__ float fast_sqrt(float x)  { float r; asm("sqrt.approx.f32 %0, %1;"  : "=f"(r) : "f"(x)); return r; }
__device__ __forceinline__ float fast_rsqrt(float x) { float r; asm("rsqrt.approx.f32 %0, %1;" : "=f"(r) : "f"(x)); return r; }
__device__ __forceinline__ float fast_rcp(float x)   { float r; asm("rcp.approx.f32 %0, %1;"   : "=f"(r) : "f"(x)); return r; }
__device__ __forceinline__ float fast_ex2(float x)   { float r; asm("ex2.approx.f32 %0, %1;"   : "=f"(r) : "f"(x)); return r; }

// =========================================================================
// merged weight transpose: out[n][permP(k)] = tf32(in[k][n])
// =========================================================================
__global__ void transpose_all_kernel(
    const float* __restrict__ Wq, const float* __restrict__ Wk,
    const float* __restrict__ Wv, const float* __restrict__ Wp,
    const float* __restrict__ W1, const float* __restrict__ W2,
    float* __restrict__ wqt, float* __restrict__ wkt,
    float* __restrict__ wvt, float* __restrict__ wpt,
    float* __restrict__ w1t, float* __restrict__ w2t) {
    __shared__ float t[32][33];
    int bid = blockIdx.x;
    const float* in;
    float* out;
    int R, C, tl;
    if (bid < 2304) {
        int seg = bid / 576;
        tl = bid - seg * 576;
        R = 768; C = 768;
        in  = (seg == 0) ? Wq  : (seg == 1) ? Wk  : (seg == 2) ? Wv  : Wp;
        out = (seg == 0) ? wqt : (seg == 1) ? wkt : (seg == 2) ? wvt : wpt;
    } else if (bid < 3456) {
        tl = bid - 2304;
        R = 768; C = 1536;
        in = W1; out = w1t;
    } else {
        tl = bid - 3456;
        R = 1536; C = 768;
        in = W2; out = w2t;
    }
    int tilesX = C >> 5;
    int c0 = (tl % tilesX) << 5, r0 = (tl / tilesX) << 5;
    int tx = threadIdx.x, ty = threadIdx.y;
    t[ty][tx] = in[(size_t)(r0 + ty) * C + c0 + tx];
    __syncthreads();
    out[(size_t)(c0 + ty) * R + permP(r0 + tx)] = roundtf(t[tx][ty]);
}

// =========================================================================
// cp.async double-buffered mma.sync tf32 GEMM with K-permuted operands.
// smem: 2 stages x (A[128][40] + B[128][40]) = 20480 u32 = 81920 B
// Fragment loads are LDS.64 (conflict-free with pad 40).
// act: 0 plain, 1 gelu+round+PERM store, 2 round+plain store
// =========================================================================
__device__ __forceinline__ void gemm_body(
    const float* __restrict__ A, const float* __restrict__ Bt,
    const float* __restrict__ bias, float* __restrict__ C,
    int M, int N, int K, int act, uint32_t* dynsm) {
    int tid = threadIdx.x;
    int lane = tid & 31, warp = tid >> 5;
    int wm = warp >> 2, wn = warp & 3;
    int g = lane >> 2, t4 = lane & 3;
    int m0 = blockIdx.y << 7, n0 = blockIdx.x << 7;

    float acc[4][4][4];
#pragma unroll
    for (int i = 0; i < 4; i++)
#pragma unroll
        for (int j = 0; j < 4; j++)
#pragma unroll
            for (int r = 0; r < 4; r++) acc[i][j][r] = 0.f;

    int rowL[4], qL[4];
#pragma unroll
    for (int it = 0; it < 4; it++) {
        int e = (it << 8) + tid;
        rowL[it] = e >> 3;
        qL[it] = (e & 7) << 2;
    }
    const float* aPtr[4];
    const float* bPtr[4];
    uint32_t aOff[4], bOff[4];
    uint32_t sbase = smem_u32(dynsm);
#pragma unroll
    for (int it = 0; it < 4; it++) {
        aPtr[it] = A + (size_t)(m0 + rowL[it]) * K + qL[it];
        bPtr[it] = Bt + (size_t)(n0 + rowL[it]) * K + qL[it];
        aOff[it] = sbase + (uint32_t)(rowL[it] * 40 + qL[it]) * 4;
        bOff[it] = aOff[it] + 5120u * 4u;
    }

    const int NT = K >> 5;
#pragma unroll
    for (int it = 0; it < 4; it++) {
        cp_async16(aOff[it], aPtr[it]);
        cp_async16(bOff[it], bPtr[it]);
    }
    CP_COMMIT();

    for (int kt = 0; kt < NT; kt++) {
        int buf = kt & 1;
        CP_WAIT_ALL();
        __syncthreads();
        if (kt + 1 < NT) {
            int kb = (kt + 1) << 5;
            uint32_t boff = (kt + 1) & 1 ? 10240u * 4u : 0u;
#pragma unroll
            for (int it = 0; it < 4; it++) {
                cp_async16(aOff[it] + boff, aPtr[it] + kb);
                cp_async16(bOff[it] + boff, bPtr[it] + kb);
            }
            CP_COMMIT();
        }

        const uint2* Ab2 = (const uint2*)(dynsm + buf * 10240);
        const uint2* Bb2 = (const uint2*)(dynsm + buf * 10240 + 5120);
#pragma unroll
        for (int kf = 0; kf < 4; kf++) {
            int kq = (kf << 2) + t4;   // uint2 col index within row (row*20 + kq)
            uint32_t af[4][4], bf[4][2];
#pragma unroll
            for (int mi = 0; mi < 4; mi++) {
                int row = (wm << 6) + (mi << 4) + g;
                uint2 a02 = Ab2[row * 20 + kq];
                uint2 a13 = Ab2[(row + 8) * 20 + kq];
                af[mi][0] = a02.x;
                af[mi][1] = a13.x;
                af[mi][2] = a02.y;
                af[mi][3] = a13.y;
            }
#pragma unroll
            for (int ni = 0; ni < 4; ni++) {
                int nr = (wn << 5) + (ni << 3) + g;
                uint2 b01 = Bb2[nr * 20 + kq];
                bf[ni][0] = b01.x;
                bf[ni][1] = b01.y;
            }
#pragma unroll
            for (int mi = 0; mi < 4; mi++)
#pragma unroll
                for (int ni = 0; ni < 4; ni++)
                    mma_tf32(acc[mi][ni], af[mi], bf[ni]);
        }
    }

#pragma unroll
    for (int mi = 0; mi < 4; mi++) {
        int row0 = m0 + (wm << 6) + (mi << 4) + g;
#pragma unroll
        for (int ni = 0; ni < 4; ni++) {
            int col = n0 + (wn << 5) + (ni << 3) + (t4 << 1);
            float b0 = bias[col], b1 = bias[col + 1];
#pragma unroll
            for (int half = 0; half < 2; half++) {
                int row = row0 + half * 8;
                float v0 = acc[mi][ni][half * 2 + 0] + b0;
                float v1 = acc[mi][ni][half * 2 + 1] + b1;
                if (act == 1) {
                    v0 = 0.5f * v0 * (1.0f + erff(v0 * 0.70710678118654752f));
                    v1 = 0.5f * v1 * (1.0f + erff(v1 * 0.70710678118654752f));
                    v0 = roundtf(v0);
                    v1 = roundtf(v1);
                    // permuted store (output feeds the next GEMM's K dim)
                    C[(size_t)row * N + permP(col)] = v0;
                    C[(size_t)row * N + permP(col + 1)] = v1;
                } else {
                    if (act == 2) {
                        v0 = roundtf(v0);
                        v1 = roundtf(v1);
                    }
                    float2 st = make_float2(v0, v1);
                    *(float2*)(C + (size_t)row * N + col) = st;
                }
            }
        }
    }
}

__global__ __launch_bounds__(256, 2) void gemm_mma_kernel(
    const float* __restrict__ A, const float* __restrict__ Bt,
    const float* __restrict__ bias, float* __restrict__ C,
    int M, int N, int K, int act) {
    extern __shared__ uint32_t dynsm[];
    gemm_body(A, Bt, bias, C, M, N, K, act, dynsm);
}

__global__ __launch_bounds__(256, 2) void qkv_gemm_kernel(
    const float* __restrict__ lnbase, const float* __restrict__ wtbase,
    const float* __restrict__ bq, const float* __restrict__ bk,
    const float* __restrict__ bv, float* __restrict__ outbase) {
    extern __shared__ uint32_t dynsm[];
    int z = blockIdx.z;
    const float* bias = (z == 0) ? bq : ((z == 1) ? bk : bv);
    gemm_body(lnbase + (size_t)z * 3145728, wtbase + (size_t)z * 589824,
              bias, outbase + (size_t)z * 3145728, 4096, 768, 768, 2, dynsm);
}

// =========================================================================
// cp.async double-buffered flash attention (R13 core; epilogue stores att
// with K-permuted columns for the Wp GEMM)
// =========================================================================
__global__ __launch_bounds__(256) void attn_mma_kernel(
    const float* __restrict__ q, const float* __restrict__ k,
    const float* __restrict__ v, const float* __restrict__ wm,
    float* __restrict__ att_out) {
    extern __shared__ uint32_t dynsm[];
    uint32_t (*Qs)[68] = (uint32_t(*)[68])(dynsm);
    const uint32_t* KSu = dynsm + 8704;
    const uint32_t* VSu = dynsm + 17408;
    const float* WSf = (const float*)(dynsm + 26624);
    uint32_t (*Ps)[68] = (uint32_t(*)[68])(dynsm + 44032);

    uint32_t sbase = smem_u32(dynsm);
    uint32_t kByte = sbase + 8704u * 4u;
    uint32_t vByte = sbase + 17408u * 4u;
    uint32_t wByte = sbase + 26624u * 4u;

    int bh = blockIdx.y;
    int b = bh / 12, h = bh - b * 12;
    int q0 = blockIdx.x << 7;
    int tid = threadIdx.x;
    int lane = tid & 31, warp = tid >> 5;
    int g = lane >> 2, t4 = lane & 3;
    int r = (warp << 4) + g;

#pragma unroll
    for (int it = 0; it < 8; it++) {
        int e = (it << 8) + tid;
        int row = e >> 4, c4 = (e & 15) << 2;
        float4 qv = *(const float4*)(q + (size_t)(b * 1024 + q0 + row) * 768 + h * 64 + c4);
        Qs[row][c4 + 0] = __float_as_uint(qv.x * 0.125f);
        Qs[row][c4 + 1] = __float_as_uint(qv.y * 0.125f);
        Qs[row][c4 + 2] = __float_as_uint(qv.z * 0.125f);
        Qs[row][c4 + 3] = __float_as_uint(qv.w * 0.125f);
    }

    const float* wbase = wm + ((size_t)(b * 12) << 20);

#define LOAD_TILES(bsel, k0)                                                            \
    do {                                                                                \
        uint32_t kb_ = kByte + (uint32_t)(bsel) * 17408u;                               \
        uint32_t vb_ = vByte + (uint32_t)(bsel) * 18432u;                               \
        uint32_t wb_ = wByte + (uint32_t)(bsel) * 34816u;                               \
        _Pragma("unroll")                                                               \
        for (int it_ = 0; it_ < 4; it_++) {                                             \
            int e_ = (it_ << 8) + tid;                                                  \
            int row_ = e_ >> 4, c4_ = (e_ & 15) << 2;                                   \
            size_t ga_ = (size_t)(b * 1024 + (k0) + row_) * 768 + h * 64 + c4_;         \
            cp_async16(kb_ + (uint32_t)((row_ * 68 + c4_) << 2), k + ga_);              \
            cp_async16(vb_ + (uint32_t)((row_ * 72 + c4_) << 2), v + ga_);              \
        }                                                                               \
        _Pragma("unroll")                                                               \
        for (int it_ = 0; it_ < 8; it_++) {                                             \
            int e_ = (it_ << 8) + tid;                                                  \
            int row_ = e_ >> 4, c4_ = (e_ & 15) << 2;                                   \
            cp_async16(wb_ + (uint32_t)((row_ * 68 + c4_) << 2),                        \
                       wbase + (size_t)(q0 + row_) * 1024 + (k0) + c4_);                \
        }                                                                               \
        CP_COMMIT();                                                                    \
    } while (0)

    float of[8][4];
#pragma unroll
    for (int ni = 0; ni < 8; ni++)
#pragma unroll
        for (int j = 0; j < 4; j++) of[ni][j] = 0.f;
    float lrun_a = 0.f, lrun_b = 0.f;

    LOAD_TILES(0, 0);

    for (int kt = 0; kt < 16; kt++) {
        int buf = kt & 1;
        CP_WAIT_ALL();
        __syncthreads();
        if (kt + 1 < 16) LOAD_TILES((kt + 1) & 1, (kt + 1) << 6);

        const uint32_t* Kb = KSu + buf * 4352;
        const uint32_t* Vb = VSu + buf * 4608;
        const float* Wb = WSf + buf * 8704;

        float sacc[8][4];
#pragma unroll
        for (int ni = 0; ni < 8; ni++)
#pragma unroll
            for (int j = 0; j < 4; j++) sacc[ni][j] = 0.f;
#pragma unroll
        for (int kf = 0; kf < 8; kf++) {
            int kc = kf << 3;
            uint32_t A[4];
            A[0] = Qs[r][kc + t4];
            A[1] = Qs[r + 8][kc + t4];
            A[2] = Qs[r][kc + t4 + 4];
            A[3] = Qs[r + 8][kc + t4 + 4];
#pragma unroll
            for (int ni = 0; ni < 8; ni++) {
                const uint32_t* krow = Kb + ((ni << 3) + g) * 68;
                uint32_t B[2];
                B[0] = krow[kc + t4];
                B[1] = krow[kc + t4 + 4];
                mma_tf32(sacc[ni], A, B);
            }
        }

        const float* wr0 = Wb + r * 68;
        const float* wr1 = Wb + (r + 8) * 68;
        float sum_a = 0.f, sum_b = 0.f;
#pragma unroll
        for (int ni = 0; ni < 8; ni++) {
            int c0 = (ni << 3) + (t4 << 1);
            float p0 = __expf(sacc[ni][0] * wr0[c0]);
            float p1 = __expf(sacc[ni][1] * wr0[c0 + 1]);
            float p2 = __expf(sacc[ni][2] * wr1[c0]);
            float p3 = __expf(sacc[ni][3] * wr1[c0 + 1]);
            sum_a += p0 + p1;
            sum_b += p2 + p3;
            Ps[r][c0] = f2tf32(p0);
            Ps[r][c0 + 1] = f2tf32(p1);
            Ps[r + 8][c0] = f2tf32(p2);
            Ps[r + 8][c0 + 1] = f2tf32(p3);
        }
        sum_a += __shfl_xor_sync(0xffffffffu, sum_a, 1);
        sum_a += __shfl_xor_sync(0xffffffffu, sum_a, 2);
        sum_b += __shfl_xor_sync(0xffffffffu, sum_b, 1);
        sum_b += __shfl_xor_sync(0xffffffffu, sum_b, 2);
        lrun_a += sum_a;
        lrun_b += sum_b;

        __syncwarp();

#pragma unroll
        for (int kf = 0; kf < 8; kf++) {
            int kc = kf << 3;
            uint32_t A[4];
            A[0] = Ps[r][kc + t4];
            A[1] = Ps[r + 8][kc + t4];
            A[2] = Ps[r][kc + t4 + 4];
            A[3] = Ps[r + 8][kc + t4 + 4];
            const uint32_t* v0r = Vb + (kc + t4) * 72;
            const uint32_t* v1r = Vb + (kc + t4 + 4) * 72;
#pragma unroll
            for (int ni = 0; ni < 8; ni++) {
                int d = (ni << 3) + g;
                uint32_t B[2];
                B[0] = v0r[d];
                B[1] = v1r[d];
                mma_tf32(of[ni], A, B);
            }
        }
    }

    float ia = 1.0f / lrun_a, ib = 1.0f / lrun_b;
#pragma unroll
    for (int ni = 0; ni < 8; ni++) {
        int colbase = h * 64 + (ni << 3);
        int c0 = t4 << 1;
        int p0c = permP(c0), p1c = permP(c0 + 1);
        float* o0 = att_out + (size_t)(b * 1024 + q0 + r) * 768 + colbase;
        float* o1 = att_out + (size_t)(b * 1024 + q0 + r + 8) * 768 + colbase;
        o0[p0c] = roundtf(of[ni][0] * ia);
        o0[p1c] = roundtf(of[ni][1] * ia);
        o1[p0c] = roundtf(of[ni][2] * ib);
        o1[p1c] = roundtf(of[ni][3] * ib);
    }
#undef LOAD_TILES
}

// =========================================================================
// epipolar parameter setup (unchanged)
// =========================================================================
__global__ void setup_params_kernel(const float* __restrict__ intr,
                                    const float* __restrict__ c2w) {
    int t = threadIdx.x;
    if (t >= 8) return;
    int dir = t >> 2, b = t & 3;

    float k3[3][3];
    const float Wf = 32.0f * 16.0f / 9.0f;
    for (int i = 0; i < 3; i++)
        for (int j = 0; j < 3; j++)
            k3[i][j] = intr[b * 16 + i * 4 + j];
    for (int j = 0; j < 3; j++) { k3[0][j] *= Wf; k3[1][j] *= 32.0f; }
    k3[0][2] = 16.0f; k3[1][2] = 16.0f;

    int si = (dir == 0) ? 1 : 0;
    int ti = (dir == 0) ? 0 : 1;
    const float* S = c2w + (si * 4 + b) * 16;
    const float* T = c2w + (ti * 4 + b) * 16;
    float sr[3][3], st[3], tr[3][3], tt[3];
    for (int i = 0; i < 3; i++) {
        for (int j = 0; j < 3; j++) { sr[i][j] = S[i * 4 + j]; tr[i][j] = T[i * 4 + j]; }
        st[i] = S[i * 4 + 3]; tt[i] = T[i * 4 + 3];
    }
    float det = tr[0][0] * (tr[1][1] * tr[2][2] - tr[1][2] * tr[2][1])
              - tr[0][1] * (tr[1][0] * tr[2][2] - tr[1][2] * tr[2][0])
              + tr[0][2] * (tr[1][0] * tr[2][1] - tr[1][1] * tr[2][0]);
    float id = 1.0f / det;
    float ti3[3][3];
    ti3[0][0] = (tr[1][1] * tr[2][2] - tr[1][2] * tr[2][1]) * id;
    ti3[0][1] = (tr[0][2] * tr[2][1] - tr[0][1] * tr[2][2]) * id;
    ti3[0][2] = (tr[0][1] * tr[1][2] - tr[0][2] * tr[1][1]) * id;
    ti3[1][0] = (tr[1][2] * tr[2][0] - tr[1][0] * tr[2][2]) * id;
    ti3[1][1] = (tr[0][0] * tr[2][2] - tr[0][2] * tr[2][0]) * id;
    ti3[1][2] = (tr[0][2] * tr[1][0] - tr[0][0] * tr[1][2]) * id;
    ti3[2][0] = (tr[1][0] * tr[2][1] - tr[1][1] * tr[2][0]) * id;
    ti3[2][1] = (tr[0][1] * tr[2][0] - tr[0][0] * tr[2][1]) * id;
    ti3[2][2] = (tr[0][0] * tr[1][1] - tr[0][1] * tr[1][0]) * id;

    float TR[3][3], Mm[3][3];
    for (int i = 0; i < 3; i++)
        for (int j = 0; j < 3; j++) {
            float s = 0.f;
            for (int kk = 0; kk < 3; kk++) s += ti3[i][kk] * sr[kk][j];
            TR[i][j] = s;
        }
    for (int i = 0; i < 3; i++)
        for (int j = 0; j < 3; j++) {
            float s = 0.f;
            for (int kk = 0; kk < 3; kk++) s += k3[i][kk] * TR[kk][j];
            Mm[i][j] = s;
        }
    float o2[3], tv[3];
    for (int i = 0; i < 3; i++) {
        float s = 0.f;
        for (int kk = 0; kk < 3; kk++) s += ti3[i][kk] * st[kk];
        o2[i] = s - tt[i];
    }
    for (int i = 0; i < 3; i++) {
        float s = 0.f;
        for (int kk = 0; kk < 3; kk++) s += k3[i][kk] * o2[kk];
        tv[i] = s;
    }
    float* P = g_params[t];
    P[0] = Mm[0][0]; P[1] = Mm[0][1]; P[2] = Mm[0][2];
    P[3] = Mm[1][0]; P[4] = Mm[1][1]; P[5] = Mm[1][2];
    P[6] = Mm[2][0]; P[7] = Mm[2][1]; P[8] = Mm[2][2];
    P[9] = tv[0]; P[10] = tv[1]; P[11] = tv[2];
    P[12] = k3[0][0]; P[13] = k3[1][1]; P[14] = k3[0][2]; P[15] = k3[1][2];
}

// =========================================================================
// epipolar rows — band-skip fast-math (unchanged)
// =========================================================================
__global__ void epipolar_kernel(float* __restrict__ ep) {
    int i = blockIdx.x, b = blockIdx.y, dir = blockIdx.z;
    const float* P = g_params[dir * 4 + b];
    float M0 = P[0], M1 = P[1], M2 = P[2], M3 = P[3], M4 = P[4], M5 = P[5],
          M6 = P[6], M7 = P[7], M8 = P[8];
    float tv0 = P[9], tv1 = P[10], tv2 = P[11];
    float fx = P[12], fy = P[13], cx = P[14], cy = P[15];

    float ncx = ((float)(i & 31) - cx) / fx;
    float ncy = ((float)(i >> 5) - cy) / fy;
    float pux = M0 * ncx + M1 * ncy + M2 + tv0;
    float puy = M3 * ncx + M4 * ncy + M5 + tv1;
    float puz = M6 * ncx + M7 * ncy + M8 + tv2;
    float invz = 1.0f / (puz + 1e-6f);
    float px = pux * invz, py = puy * invz, pz = puz * invz;
    float ozi = 1.0f / tv2;
    float ox = tv0 * ozi, oy = tv1 * ozi, oz = tv2 * ozi;
    float ax = px - ox, ay = py - oy, az = pz - oz;
    float vlen2 = ax * ax + ay * ay + az * az;
    float inv_vlen = fast_rsqrt(vlen2);
    float inv_vlen2 = inv_vlen * inv_vlen;
    float bz = 1.0f - oz;

    const float C1 = 72.13475204444817f;
    const float C0 = -36.067376022224085f;
    const float HI2 = 0.85f * 0.85f;
    const float LO2 = 0.15f * 0.15f;

    int tid = threadIdx.x;
    float dwv[4];
    float lmax = -1e30f;
#pragma unroll
    for (int it = 0; it < 4; it++) {
        int j = tid + it * 256;
        float bx = (float)(j & 31) - ox;
        float by = (float)(j >> 5) - oy;
        float crx = ay * bz - az * by;
        float cry = az * bx - ax * bz;
        float crz = ax * by - ay * bx;
        float a2 = crx * crx + cry * cry + crz * crz;
        float d2 = a2 * inv_vlen2;
        float dw;
        if (d2 >= HI2) {
            dw = 0.0f;
        } else if (d2 <= LO2) {
            dw = 1.0f;
        } else {
            float dist = fast_sqrt(a2) * inv_vlen;
            float e = fast_ex2(C1 * dist + C0);
            dw = fast_rcp(1.0f + e);
        }
        dwv[it] = dw;
        lmax = fmaxf(lmax, dw);
    }
    __shared__ float red[256];
    red[tid] = lmax;
    __syncthreads();
    for (int s = 128; s > 0; s >>= 1) {
        if (tid < s) red[tid] = fmaxf(red[tid], red[tid + s]);
        __syncthreads();
    }
    float rmax = red[0];
    float* dst = ep + ((size_t)((dir * 4 + b) * 1024 + i) << 10);
#pragma unroll
    for (int it = 0; it < 4; it++) {
        int j = tid + it * 256;
        dst[j] = (rmax < 0.5f) ? 1.0f : dwv[it];
    }
}

// =========================================================================
// wmap: float4-vectorized (unchanged)
// =========================================================================
__global__ void wmap_kernel(const float* __restrict__ ep,
                            float* __restrict__ out_wm) {
    int b = blockIdx.z;
    int I0 = blockIdx.y << 5, J0 = blockIdx.x << 5;
    int tid = threadIdx.x;
    __shared__ float s1[32][33];
    const float* e0 = ep + ((size_t)(b * 1024) << 10);
    const float* e1 = ep + ((size_t)((4 + b) * 1024) << 10);

    {
        int j = tid >> 3, i4 = (tid & 7) << 2;
        float4 vv = *(const float4*)(e1 + (size_t)(J0 + j) * 1024 + I0 + i4);
        s1[j][i4 + 0] = vv.x;
        s1[j][i4 + 1] = vv.y;
        s1[j][i4 + 2] = vv.z;
        s1[j][i4 + 3] = vv.w;
    }
    __syncthreads();

    int i = tid >> 3, jq = (tid & 7) << 2;
    float4 a = *(const float4*)(e0 + (size_t)(I0 + i) * 1024 + J0 + jq);
    float4 w;
    w.x = a.x * s1[jq + 0][i];
    w.y = a.y * s1[jq + 1][i];
    w.z = a.z * s1[jq + 2][i];
    w.w = a.w * s1[jq + 3][i];
    size_t off = (size_t)(I0 + i) * 1024 + J0 + jq;
    float* dst = out_wm + (((size_t)(b * 12)) << 20) + off;
#pragma unroll
    for (int h = 0; h < 12; h++)
        *(float4*)(dst + ((size_t)h << 20)) = w;
}

// =========================================================================
// layernorm body: optional residual, optional tf32 round, optional
// K-permuted output, optional plain second output (for residual reuse)
// =========================================================================
__device__ __forceinline__ void ln_body(const float* __restrict__ in,
                                        const float* __restrict__ res,
                                        const float* __restrict__ gam,
                                        const float* __restrict__ bet,
                                        float* __restrict__ out, int rnd,
                                        int perm, float* __restrict__ out2) {
    int row = (blockIdx.x << 3) + (threadIdx.x >> 5);
    int lane = threadIdx.x & 31;
    const float* p = in + (size_t)row * 768;
    float v[24];
    float s = 0.f;
#pragma unroll
    for (int it = 0; it < 24; it++) {
        int c = lane + (it << 5);
        v[it] = p[c];
        if (res) v[it] += res[(size_t)row * 768 + c];
        s += v[it];
    }
#pragma unroll
    for (int o = 16; o > 0; o >>= 1) s += __shfl_xor_sync(0xffffffffu, s, o);
    float mu = s * (1.0f / 768.0f);
    float qsum = 0.f;
#pragma unroll
    for (int it = 0; it < 24; it++) {
        float d = v[it] - mu;
        qsum += d * d;
    }
#pragma unroll
    for (int o = 16; o > 0; o >>= 1) qsum += __shfl_xor_sync(0xffffffffu, qsum, o);
    float rstd = rsqrtf(qsum * (1.0f / 768.0f) + 1e-5f);
#pragma unroll
    for (int it = 0; it < 24; it++) {
        int c = lane + (it << 5);
        float val = (v[it] - mu) * rstd * gam[c] + bet[c];
        if (rnd) val = roundtf(val);
        int oc = perm ? permP(c) : c;
        out[(size_t)row * 768 + oc] = val;
        if (out2) out2[(size_t)row * 768 + c] = val;
    }
}

__global__ void ln_kernel(const float* __restrict__ in, const float* __restrict__ res,
                          const float* __restrict__ gam, const float* __restrict__ bet,
                          float* __restrict__ out, int rnd, int perm,
                          float* __restrict__ out2) {
    ln_body(in, res, gam, bet, out, rnd, perm, out2);
}

__global__ void ln3_kernel(const float* __restrict__ x, const float* __restrict__ src,
                           const float* __restrict__ gq, const float* __restrict__ bq,
                           const float* __restrict__ gk, const float* __restrict__ bk,
                           const float* __restrict__ gv, const float* __restrict__ bv,
                           float* __restrict__ outbase) {
    int z = blockIdx.y;
    const float* in = (z == 0) ? x : src;
    const float* gam = (z == 0) ? gq : ((z == 1) ? gk : gv);
    const float* bet = (z == 0) ? bq : ((z == 1) ? bk : bv);
    ln_body(in, nullptr, gam, bet, outbase + (size_t)z * 3145728, 1, 1, nullptr);
}

// =========================================================================
// launch
// =========================================================================
extern "C" void kernel_launch(void* const* d_in, const int* in_sizes, int n_in,
                              void* d_out, int out_size) {
    const float* x      = (const float*)d_in[0];
    const float* src    = (const float*)d_in[1];
    const float* intr   = (const float*)d_in[2];
    const float* c2w    = (const float*)d_in[3];
    const float* lnq_g  = (const float*)d_in[4];
    const float* lnq_b  = (const float*)d_in[5];
    const float* Wq     = (const float*)d_in[6];
    const float* bq     = (const float*)d_in[7];
    const float* lnk_g  = (const float*)d_in[8];
    const float* lnk_b  = (const float*)d_in[9];
    const float* Wk     = (const float*)d_in[10];
    const float* bk     = (const float*)d_in[11];
    const float* lnv_g  = (const float*)d_in[12];
    const float* lnv_b  = (const float*)d_in[13];
    const float* Wv     = (const float*)d_in[14];
    const float* bv     = (const float*)d_in[15];
    const float* Wp     = (const float*)d_in[16];
    const float* bp     = (const float*)d_in[17];
    const float* pre_g  = (const float*)d_in[18];
    const float* pre_b  = (const float*)d_in[19];
    const float* W1     = (const float*)d_in[20];
    const float* b1     = (const float*)d_in[21];
    const float* W2     = (const float*)d_in[22];
    const float* b2     = (const float*)d_in[23];
    const float* post_g = (const float*)d_in[24];
    const float* post_b = (const float*)d_in[25];

    float* out_z  = (float*)d_out;
    float* out_wm = out_z + (size_t)4 * 1024 * 768;

    void* sp = nullptr;
    cudaGetSymbolAddress(&sp, g_scratch);
    float* base = (float*)sp;
    float* ep   = base + OFF_EP;
    float* z0p  = base + OFF_EP;        // reuse ep region after wmap: plain z0 copy
    float* lnx  = base + OFF_LNX;
    float* qb   = base + OFF_Q;
    float* kb   = qb + 3145728;
    float* vb   = kb + 3145728;
    float* att  = base + OFF_ATT;
    float* p0   = base + OFF_P0;
    float* z0   = base + OFF_Z0;
    float* hid  = base + OFF_HID;
    float* wqt  = base + OFF_WQT;
    float* wkt  = wqt + 589824;
    float* wvt  = wkt + 589824;
    float* wpt  = base + OFF_WPT;
    float* w1t  = base + OFF_W1T;
    float* w2t  = base + OFF_W2T;

    cudaFuncSetAttribute(attn_mma_kernel,
                         cudaFuncAttributeMaxDynamicSharedMemorySize, 210944);
    cudaFuncSetAttribute(gemm_mma_kernel,
                         cudaFuncAttributeMaxDynamicSharedMemorySize, 81920);
    cudaFuncSetAttribute(qkv_gemm_kernel,
                         cudaFuncAttributeMaxDynamicSharedMemorySize, 81920);

    dim3 tb(32, 32);
    transpose_all_kernel<<<4608, tb>>>(Wq, Wk, Wv, Wp, W1, W2,
                                       wqt, wkt, wvt, wpt, w1t, w2t);

    setup_params_kernel<<<1, 8>>>(intr, c2w);
    epipolar_kernel<<<dim3(1024, 4, 2), 256>>>(ep);
    wmap_kernel<<<dim3(32, 32, 4), 256>>>(ep, out_wm);

    ln3_kernel<<<dim3(512, 3), 256>>>(x, src, lnq_g, lnq_b, lnk_g, lnk_b,
                                      lnv_g, lnv_b, lnx);

    qkv_gemm_kernel<<<dim3(6, 32, 3), 256, 81920>>>(lnx, wqt, bq, bk, bv, qb);

    attn_mma_kernel<<<dim3(8, 48), 256, 210944>>>(qb, kb, vb, out_wm, att);

    // Wp: A=att (perm), output p0 plain
    gemm_mma_kernel<<<dim3(6, 32), 256, 81920>>>(att, wpt, bp, p0, 4096, 768, 768, 0);
    // pre-LN: reads plain p0, writes z0 (perm, for W1) + z0p (plain, for residual)
    ln_kernel<<<512, 256>>>(p0, nullptr, pre_g, pre_b, z0, 1, 1, z0p);
    // W1: A=z0 (perm), gelu epilogue writes hid PERMUTED (act=1)
    gemm_mma_kernel<<<dim3(12, 32), 256, 81920>>>(z0, w1t, b1, hid, 4096, 1536, 768, 1);
    // W2: A=hid (perm), output p0 plain
    gemm_mma_kernel<<<dim3(6, 32), 256, 81920>>>(hid, w2t, b2, p0, 4096, 768, 1536, 0);
    // post-LN: plain in, plain residual, plain out
    ln_kernel<<<512, 256>>>(p0, z0p, post_g, post_b, out_z, 0, 0, nullptr);
}